// round 4
// baseline (speedup 1.0000x reference)
#include <cuda_runtime.h>
#include <math.h>

#define BB   64
#define TIN  128
#define NIN  256
#define MM   1024
#define OO   512
#define LMM  2048
#define TDEC 64
#define G3   3072   // 3*MM

// ---------------- scratch (device globals; no allocations allowed) ----------
__device__ float g_xt[TIN * BB * NIN];            // X transposed to [t][b][n]
__device__ float g_gi[TIN * BB * G3];             // precomputed input gates
__device__ float g_seq0[TIN * BB * MM];           // encoder layer0 outputs
__device__ float g_e0A[BB * MM], g_e0B[BB * MM];
__device__ float g_e1A[BB * MM], g_e1B[BB * MM];
__device__ float g_yA[BB * OO], g_yB[BB * OO];
__device__ float g_zpre[BB * LMM];
__device__ float g_z[BB * LMM];
__device__ float g_z2p[4 * BB * OO];

// ---------------- f32x2 packed-FMA helpers ----------------
__device__ __forceinline__ unsigned long long pk2(float lo, float hi) {
    unsigned long long r;
    asm("mov.b64 %0, {%1,%2};" : "=l"(r) : "f"(lo), "f"(hi));
    return r;
}
__device__ __forceinline__ void fma2(unsigned long long& d, unsigned long long a, unsigned long long b) {
    asm("fma.rn.f32x2 %0, %1, %2, %0;" : "+l"(d) : "l"(a), "l"(b));
}
__device__ __forceinline__ float2 upk(unsigned long long v) {
    float2 f;
    asm("mov.b64 {%0,%1}, %2;" : "=f"(f.x), "=f"(f.y) : "l"(v));
    return f;
}
__device__ __forceinline__ float sigf(float x) { return 1.f / (1.f + expf(-x)); }

// ---------------- utility kernels ----------------
__global__ void zero_init_kernel() {
    int i = blockIdx.x * blockDim.x + threadIdx.x;
    int stride = gridDim.x * blockDim.x;
    for (; i < BB * MM; i += stride) { g_e0A[i] = 0.f; g_e1A[i] = 0.f; }
}

__global__ void copy_y_kernel(const float* __restrict__ Y0) {
    int i = blockIdx.x * blockDim.x + threadIdx.x;
    if (i < BB * OO) g_yA[i] = Y0[i];
}

__global__ void transpose_x_kernel(const float* __restrict__ X) {
    int i = blockIdx.x * blockDim.x + threadIdx.x;
    int stride = gridDim.x * blockDim.x;
    const int total = TIN * BB * NIN;
    for (; i < total; i += stride) {
        int n = i % NIN;
        int r = i / NIN;
        int t = r / BB;
        int b = r % BB;
        g_xt[i] = X[(b * TIN + t) * NIN + n];
    }
}

// ---------------- big GEMM: C[R][Cn] = A[R][K] @ W[Cn][K]^T + bias ----------
// 128x128 tile, 256 threads, 8x8 per thread, f32x2 accumulation (col pairs)
__global__ void __launch_bounds__(256) gemm_big_kernel(
    const float* __restrict__ A, const float* __restrict__ W,
    const float* __restrict__ bias, float* __restrict__ C,
    int K, int Cn)
{
    __shared__ __align__(16) float As[16][132];
    __shared__ __align__(16) float Bs[16][132];
    int tid = threadIdx.x;
    int tx = tid & 15;           // 8 cols each
    int ty = tid >> 4;           // 8 rows each
    int r0 = blockIdx.y * 128;
    int c0 = blockIdx.x * 128;

    unsigned long long acc[8][4];
#pragma unroll
    for (int i = 0; i < 8; i++)
#pragma unroll
        for (int j = 0; j < 4; j++) acc[i][j] = 0ull;

    for (int k0 = 0; k0 < K; k0 += 16) {
#pragma unroll
        for (int i = 0; i < 2; i++) {
            int q = tid + i * 256;
            int rr = q >> 2, kq = q & 3;
            float4 v = *(const float4*)(A + (size_t)(r0 + rr) * K + k0 + kq * 4);
            As[kq * 4 + 0][rr] = v.x; As[kq * 4 + 1][rr] = v.y;
            As[kq * 4 + 2][rr] = v.z; As[kq * 4 + 3][rr] = v.w;
        }
#pragma unroll
        for (int i = 0; i < 2; i++) {
            int q = tid + i * 256;
            int wn = q >> 2, kq = q & 3;
            float4 v = *(const float4*)(W + (size_t)(c0 + wn) * K + k0 + kq * 4);
            Bs[kq * 4 + 0][wn] = v.x; Bs[kq * 4 + 1][wn] = v.y;
            Bs[kq * 4 + 2][wn] = v.z; Bs[kq * 4 + 3][wn] = v.w;
        }
        __syncthreads();
#pragma unroll
        for (int kk = 0; kk < 16; kk++) {
            float4 b0 = *(float4*)&Bs[kk][tx * 8];
            float4 b1 = *(float4*)&Bs[kk][tx * 8 + 4];
            unsigned long long bp[4] = {pk2(b0.x, b0.y), pk2(b0.z, b0.w),
                                        pk2(b1.x, b1.y), pk2(b1.z, b1.w)};
            float4 a0 = *(float4*)&As[kk][ty * 8];
            float4 a1 = *(float4*)&As[kk][ty * 8 + 4];
            float av[8] = {a0.x, a0.y, a0.z, a0.w, a1.x, a1.y, a1.z, a1.w};
#pragma unroll
            for (int i = 0; i < 8; i++) {
                unsigned long long ap = pk2(av[i], av[i]);
#pragma unroll
                for (int j = 0; j < 4; j++) fma2(acc[i][j], ap, bp[j]);
            }
        }
        __syncthreads();
    }

    int c = c0 + tx * 8;
    float4 bv0 = *(const float4*)(bias + c);
    float4 bv1 = *(const float4*)(bias + c + 4);
#pragma unroll
    for (int i = 0; i < 8; i++) {
        int r = r0 + ty * 8 + i;
        float2 p0 = upk(acc[i][0]), p1 = upk(acc[i][1]);
        float2 p2 = upk(acc[i][2]), p3 = upk(acc[i][3]);
        float4 o0 = {p0.x + bv0.x, p0.y + bv0.y, p1.x + bv0.z, p1.y + bv0.w};
        float4 o1 = {p2.x + bv1.x, p2.y + bv1.y, p3.x + bv1.z, p3.y + bv1.w};
        *(float4*)(C + (size_t)r * Cn + c) = o0;
        *(float4*)(C + (size_t)r * Cn + c + 4) = o1;
    }
}

// ---------------- fused GRU step ----------------
// grid 256 blocks (4 n-cols each), 128 threads.
// thread: p = tid&1 -> col pair (c0+2p, c0+2p+1); row = tid>>1 (0..63).
// HAS_GI: input gates precomputed in gi_t. Otherwise computed from (x, Wih, bih).
template<bool HAS_GI>
__global__ void __launch_bounds__(128) gru_fused_kernel(
    const float* __restrict__ x, int Kx,
    const float* __restrict__ Wih, const float* __restrict__ bih,
    const float* __restrict__ gi_t,
    const float* __restrict__ h_in, float* __restrict__ h_out,
    float* __restrict__ seq_out,
    const float* __restrict__ Whh, const float* __restrict__ bhh)
{
    __shared__ __align__(16) float Hs[32][72];
    __shared__ __align__(16) float Ws[3][32][4];
    int tid = threadIdx.x;
    int p = tid & 1;
    int row = tid >> 1;
    int c0 = blockIdx.x * 4;
    int cc = 2 * p;
    int c = c0 + cc;

    unsigned long long aR = 0ull, aZ = 0ull, aN = 0ull;
    unsigned long long iR = 0ull, iZ = 0ull, iN = 0ull;

    if (!HAS_GI) {
        for (int k0 = 0; k0 < Kx; k0 += 32) {
#pragma unroll
            for (int i = 0; i < 4; i++) {
                int q = tid + i * 128;
                int rr = q >> 3, kq = q & 7;
                float4 v = *(const float4*)(x + (size_t)rr * Kx + k0 + kq * 4);
                Hs[kq * 4 + 0][rr] = v.x; Hs[kq * 4 + 1][rr] = v.y;
                Hs[kq * 4 + 2][rr] = v.z; Hs[kq * 4 + 3][rr] = v.w;
            }
            if (tid < 96) {
                int gcol = tid >> 3;
                int g = gcol >> 2, lc = gcol & 3;
                int kq = tid & 7;
                float4 v = *(const float4*)(Wih + (size_t)(g * MM + c0 + lc) * Kx + k0 + kq * 4);
                Ws[g][kq * 4 + 0][lc] = v.x; Ws[g][kq * 4 + 1][lc] = v.y;
                Ws[g][kq * 4 + 2][lc] = v.z; Ws[g][kq * 4 + 3][lc] = v.w;
            }
            __syncthreads();
#pragma unroll
            for (int kk = 0; kk < 32; kk++) {
                float h = Hs[kk][row];
                unsigned long long h2 = pk2(h, h);
                unsigned long long wr = *(const unsigned long long*)&Ws[0][kk][cc];
                unsigned long long wz = *(const unsigned long long*)&Ws[1][kk][cc];
                unsigned long long wn = *(const unsigned long long*)&Ws[2][kk][cc];
                fma2(iR, h2, wr); fma2(iZ, h2, wz); fma2(iN, h2, wn);
            }
            __syncthreads();
        }
    }

    for (int k0 = 0; k0 < MM; k0 += 32) {
#pragma unroll
        for (int i = 0; i < 4; i++) {
            int q = tid + i * 128;
            int rr = q >> 3, kq = q & 7;
            float4 v = *(const float4*)(h_in + (size_t)rr * MM + k0 + kq * 4);
            Hs[kq * 4 + 0][rr] = v.x; Hs[kq * 4 + 1][rr] = v.y;
            Hs[kq * 4 + 2][rr] = v.z; Hs[kq * 4 + 3][rr] = v.w;
        }
        if (tid < 96) {
            int gcol = tid >> 3;
            int g = gcol >> 2, lc = gcol & 3;
            int kq = tid & 7;
            float4 v = *(const float4*)(Whh + (size_t)(g * MM + c0 + lc) * MM + k0 + kq * 4);
            Ws[g][kq * 4 + 0][lc] = v.x; Ws[g][kq * 4 + 1][lc] = v.y;
            Ws[g][kq * 4 + 2][lc] = v.z; Ws[g][kq * 4 + 3][lc] = v.w;
        }
        __syncthreads();
#pragma unroll
        for (int kk = 0; kk < 32; kk++) {
            float h = Hs[kk][row];
            unsigned long long h2 = pk2(h, h);
            unsigned long long wr = *(const unsigned long long*)&Ws[0][kk][cc];
            unsigned long long wz = *(const unsigned long long*)&Ws[1][kk][cc];
            unsigned long long wn = *(const unsigned long long*)&Ws[2][kk][cc];
            fma2(aR, h2, wr); fma2(aZ, h2, wz); fma2(aN, h2, wn);
        }
        __syncthreads();
    }

    float2 hr = upk(aR), hz = upk(aZ), hn = upk(aN);
    float gr0, gr1, gz0, gz1, gn0, gn1;
    if (HAS_GI) {
        const float* gi = gi_t + (size_t)row * G3;
        gr0 = gi[c];          gr1 = gi[c + 1];
        gz0 = gi[MM + c];     gz1 = gi[MM + c + 1];
        gn0 = gi[2 * MM + c]; gn1 = gi[2 * MM + c + 1];
    } else {
        float2 ir2 = upk(iR), iz2 = upk(iZ), in2 = upk(iN);
        gr0 = ir2.x + bih[c];          gr1 = ir2.y + bih[c + 1];
        gz0 = iz2.x + bih[MM + c];     gz1 = iz2.y + bih[MM + c + 1];
        gn0 = in2.x + bih[2 * MM + c]; gn1 = in2.y + bih[2 * MM + c + 1];
    }
    float br0 = bhh[c],          br1 = bhh[c + 1];
    float bz0 = bhh[MM + c],     bz1 = bhh[MM + c + 1];
    float bn0 = bhh[2 * MM + c], bn1 = bhh[2 * MM + c + 1];

    float2 hprev = *(const float2*)(h_in + (size_t)row * MM + c);

    float r0 = sigf(gr0 + hr.x + br0);
    float r1 = sigf(gr1 + hr.y + br1);
    float z0 = sigf(gz0 + hz.x + bz0);
    float z1 = sigf(gz1 + hz.y + bz1);
    float n0 = tanhf(gn0 + r0 * (hn.x + bn0));
    float n1 = tanhf(gn1 + r1 * (hn.y + bn1));
    float2 ho;
    ho.x = (1.f - z0) * n0 + z0 * hprev.x;
    ho.y = (1.f - z1) * n1 + z1 * hprev.y;
    *(float2*)(h_out + (size_t)row * MM + c) = ho;
    if (seq_out) *(float2*)(seq_out + (size_t)row * MM + c) = ho;
}

// ---------------- FC GEMM (64 rows), f32x2 ----------------
// 8 cols/block, 128 threads: tx = tid&3 -> col pair; rg = tid>>2 -> rows rg, rg+32
template <bool PARTIAL>
__global__ void __launch_bounds__(128) fc_gemm_kernel(
    const float* __restrict__ A, int K,
    const float* __restrict__ W, const float* __restrict__ bias,
    float* __restrict__ C, int Cn, int kPer)
{
    __shared__ __align__(16) float As_[32][72];
    __shared__ __align__(16) float Ws_[32][8];
    int tid = threadIdx.x;
    int tx = tid & 3;
    int rg = tid >> 2;
    int c0 = blockIdx.x * 8;
    int kStart = blockIdx.y * kPer;
    int kEnd = kStart + kPer;

    unsigned long long acc0 = 0ull, acc1 = 0ull;

    for (int k0 = kStart; k0 < kEnd; k0 += 32) {
#pragma unroll
        for (int i = 0; i < 4; i++) {
            int q = tid + i * 128;
            int rr = q >> 3, kq = q & 7;
            float4 v = *(const float4*)(A + (size_t)rr * K + k0 + kq * 4);
            As_[kq * 4 + 0][rr] = v.x; As_[kq * 4 + 1][rr] = v.y;
            As_[kq * 4 + 2][rr] = v.z; As_[kq * 4 + 3][rr] = v.w;
        }
        if (tid < 64) {
            int ccw = tid >> 3;
            int kq = tid & 7;
            float4 v = *(const float4*)(W + (size_t)(c0 + ccw) * K + k0 + kq * 4);
            Ws_[kq * 4 + 0][ccw] = v.x; Ws_[kq * 4 + 1][ccw] = v.y;
            Ws_[kq * 4 + 2][ccw] = v.z; Ws_[kq * 4 + 3][ccw] = v.w;
        }
        __syncthreads();
#pragma unroll
        for (int kk = 0; kk < 32; kk++) {
            unsigned long long wp = *(const unsigned long long*)&Ws_[kk][2 * tx];
            float h0 = As_[kk][rg];
            float h1 = As_[kk][rg + 32];
            fma2(acc0, pk2(h0, h0), wp);
            fma2(acc1, pk2(h1, h1), wp);
        }
        __syncthreads();
    }

    int c = c0 + 2 * tx;
    float2 p0 = upk(acc0), p1 = upk(acc1);
    if (PARTIAL) {
        float* Cp = C + (size_t)blockIdx.y * BB * Cn;
        *(float2*)(Cp + (size_t)rg * Cn + c) = p0;
        *(float2*)(Cp + (size_t)(rg + 32) * Cn + c) = p1;
    } else {
        float b0 = bias[c], b1 = bias[c + 1];
        float2 o0 = {p0.x + b0, p0.y + b1};
        float2 o1 = {p1.x + b0, p1.y + b1};
        *(float2*)(C + (size_t)rg * Cn + c) = o0;
        *(float2*)(C + (size_t)(rg + 32) * Cn + c) = o1;
    }
}

// ---------------- LayerNorm + exact GELU ----------------
__global__ void __launch_bounds__(256) ln_gelu_kernel(
    const float* __restrict__ zpre, float* __restrict__ z,
    const float* __restrict__ g, const float* __restrict__ bta)
{
    int b = blockIdx.x, tid = threadIdx.x;
    float v[8];
    float s = 0.f, s2 = 0.f;
#pragma unroll
    for (int j = 0; j < 8; j++) {
        float t = zpre[(size_t)b * LMM + tid + j * 256];
        v[j] = t; s += t; s2 += t * t;
    }
    __shared__ float red[64];
#pragma unroll
    for (int o = 16; o; o >>= 1) {
        s += __shfl_down_sync(0xffffffffu, s, o);
        s2 += __shfl_down_sync(0xffffffffu, s2, o);
    }
    int w = tid >> 5, l = tid & 31;
    if (l == 0) { red[w] = s; red[32 + w] = s2; }
    __syncthreads();
    if (tid == 0) {
        float a = 0.f, a2 = 0.f;
        for (int i = 0; i < 8; i++) { a += red[i]; a2 += red[32 + i]; }
        red[0] = a; red[32] = a2;
    }
    __syncthreads();
    float mu = red[0] * (1.f / (float)LMM);
    float var = red[32] * (1.f / (float)LMM) - mu * mu;
    float rs = rsqrtf(var + 1e-5f);
#pragma unroll
    for (int j = 0; j < 8; j++) {
        int c = tid + j * 256;
        float t = (v[j] - mu) * rs * g[c] + bta[c];
        z[(size_t)b * LMM + c] = t * normcdff(t);
    }
}

// ---------------- fc2 combine + logits out + softmax feedback ----------------
__global__ void __launch_bounds__(512) fc2_softmax_kernel(
    const float* __restrict__ bias, float* __restrict__ out,
    float* __restrict__ y_out, int sstep)
{
    int b = blockIdx.x, o = threadIdx.x;
    float v = g_z2p[(size_t)b * OO + o]
            + g_z2p[(size_t)BB * OO + b * OO + o]
            + g_z2p[(size_t)2 * BB * OO + b * OO + o]
            + g_z2p[(size_t)3 * BB * OO + b * OO + o]
            + bias[o];
    out[((size_t)b * TDEC + sstep) * OO + o] = v;

    __shared__ float red[16];
    __shared__ float bc;
    int w = o >> 5, l = o & 31;
    float m = v;
#pragma unroll
    for (int d = 16; d; d >>= 1) m = fmaxf(m, __shfl_down_sync(0xffffffffu, m, d));
    if (l == 0) red[w] = m;
    __syncthreads();
    if (o == 0) {
        float a = red[0];
        for (int i = 1; i < 16; i++) a = fmaxf(a, red[i]);
        bc = a;
    }
    __syncthreads();
    float e = expf(v - bc);
    float sum = e;
#pragma unroll
    for (int d = 16; d; d >>= 1) sum += __shfl_down_sync(0xffffffffu, sum, d);
    if (l == 0) red[w] = sum;
    __syncthreads();
    if (o == 0) {
        float a = 0.f;
        for (int i = 0; i < 16; i++) a += red[i];
        bc = a;
    }
    __syncthreads();
    y_out[(size_t)b * OO + o] = e / bc;
}

// ---------------- host launch ----------------
extern "C" void kernel_launch(void* const* d_in, const int* in_sizes, int n_in,
                              void* d_out, int out_size)
{
    const float* X        = (const float*)d_in[0];
    const float* Y0       = (const float*)d_in[1];
    const float* enc_Wih0 = (const float*)d_in[2];
    const float* enc_Whh0 = (const float*)d_in[3];
    const float* enc_bih0 = (const float*)d_in[4];
    const float* enc_bhh0 = (const float*)d_in[5];
    const float* enc_Wih1 = (const float*)d_in[6];
    const float* enc_Whh1 = (const float*)d_in[7];
    const float* enc_bih1 = (const float*)d_in[8];
    const float* enc_bhh1 = (const float*)d_in[9];
    const float* dec_Wih0 = (const float*)d_in[10];
    const float* dec_Whh0 = (const float*)d_in[11];
    const float* dec_bih0 = (const float*)d_in[12];
    const float* dec_bhh0 = (const float*)d_in[13];
    const float* dec_Wih1 = (const float*)d_in[14];
    const float* dec_Whh1 = (const float*)d_in[15];
    const float* dec_bih1 = (const float*)d_in[16];
    const float* dec_bhh1 = (const float*)d_in[17];
    const float* fc1_w    = (const float*)d_in[18];
    const float* fc1_b    = (const float*)d_in[19];
    const float* ln_g     = (const float*)d_in[20];
    const float* ln_b     = (const float*)d_in[21];
    const float* fc2_w    = (const float*)d_in[22];
    const float* fc2_b    = (const float*)d_in[23];
    float* out = (float*)d_out;

    float *xt, *gi, *seq0, *e0A, *e0B, *e1A, *e1B, *yA, *yB, *zpre, *z, *z2p;
    cudaGetSymbolAddress((void**)&xt,   g_xt);
    cudaGetSymbolAddress((void**)&gi,   g_gi);
    cudaGetSymbolAddress((void**)&seq0, g_seq0);
    cudaGetSymbolAddress((void**)&e0A,  g_e0A);
    cudaGetSymbolAddress((void**)&e0B,  g_e0B);
    cudaGetSymbolAddress((void**)&e1A,  g_e1A);
    cudaGetSymbolAddress((void**)&e1B,  g_e1B);
    cudaGetSymbolAddress((void**)&yA,   g_yA);
    cudaGetSymbolAddress((void**)&yB,   g_yB);
    cudaGetSymbolAddress((void**)&zpre, g_zpre);
    cudaGetSymbolAddress((void**)&z,    g_z);
    cudaGetSymbolAddress((void**)&z2p,  g_z2p);

    zero_init_kernel<<<256, 256>>>();
    copy_y_kernel<<<(BB * OO + 255) / 256, 256>>>(Y0);
    transpose_x_kernel<<<2048, 256>>>(X);

    const int R = TIN * BB; // 8192

    // ---- encoder layer 0 ----
    gemm_big_kernel<<<dim3(G3 / 128, R / 128), 256>>>(xt, enc_Wih0, enc_bih0, gi, NIN, G3);
    for (int t = 0; t < TIN; t++) {
        const float* hi = (t & 1) ? e0B : e0A;
        float* ho       = (t & 1) ? e0A : e0B;
        gru_fused_kernel<true><<<256, 128>>>(nullptr, 0, nullptr, nullptr,
                                             gi + (size_t)t * BB * G3,
                                             hi, ho, seq0 + (size_t)t * BB * MM,
                                             enc_Whh0, enc_bhh0);
    }

    // ---- encoder layer 1 ----
    gemm_big_kernel<<<dim3(G3 / 128, R / 128), 256>>>(seq0, enc_Wih1, enc_bih1, gi, MM, G3);
    for (int t = 0; t < TIN; t++) {
        const float* hi = (t & 1) ? e1B : e1A;
        float* ho       = (t & 1) ? e1A : e1B;
        gru_fused_kernel<true><<<256, 128>>>(nullptr, 0, nullptr, nullptr,
                                             gi + (size_t)t * BB * G3,
                                             hi, ho, nullptr,
                                             enc_Whh1, enc_bhh1);
    }

    // ---- decoder ----
    for (int s = 0; s < TDEC; s++) {
        const float* yin = (s & 1) ? yB : yA;
        float* yout      = (s & 1) ? yA : yB;
        const float* h0i = (s & 1) ? e0B : e0A;
        float* h0o       = (s & 1) ? e0A : e0B;
        const float* h1i = (s & 1) ? e1B : e1A;
        float* h1o       = (s & 1) ? e1A : e1B;

        gru_fused_kernel<false><<<256, 128>>>(yin, OO, dec_Wih0, dec_bih0, nullptr,
                                              h0i, h0o, nullptr, dec_Whh0, dec_bhh0);
        gru_fused_kernel<false><<<256, 128>>>(h0o, MM, dec_Wih1, dec_bih1, nullptr,
                                              h1i, h1o, nullptr, dec_Whh1, dec_bhh1);
        fc_gemm_kernel<false><<<dim3(LMM / 8, 1), 128>>>(h1o, MM, fc1_w, fc1_b, zpre, LMM, MM);
        ln_gelu_kernel<<<BB, 256>>>(zpre, z, ln_g, ln_b);
        fc_gemm_kernel<true><<<dim3(OO / 8, 4), 128>>>(z, LMM, fc2_w, nullptr, z2p, OO, LMM / 4);
        fc2_softmax_kernel<<<BB, 512>>>(fc2_b, out, yout, s);
    }
}

// round 8
// speedup vs baseline: 1.8763x; 1.8763x over previous
#include <cuda_runtime.h>
#include <math.h>

#define BB   64
#define TIN  128
#define NIN  256
#define MM   1024
#define OO   512
#define LMM  2048
#define TDEC 64
#define G3   3072
typedef unsigned long long ull;

// ---------------- scratch ----------------
__device__ float g_xt[TIN * BB * NIN];
__device__ float g_gi[TIN * BB * G3];
__device__ float g_seq0[TIN * BB * MM];
__device__ float g_e0A[BB * MM], g_e0B[BB * MM];
__device__ float g_e1A[BB * MM], g_e1B[BB * MM];
__device__ float g_yA[BB * OO], g_yB[BB * OO];
__device__ float g_zpre[BB * LMM];
__device__ float g_z[BB * LMM];
__device__ float g_logits[BB * OO];

// ---------------- helpers ----------------
__device__ __forceinline__ void fma2(ull& d, ull a, ull b) {
    asm("fma.rn.f32x2 %0, %1, %2, %0;" : "+l"(d) : "l"(a), "l"(b));
}
__device__ __forceinline__ float rsum(ull v) {
    float2 f;
    asm("mov.b64 {%0,%1}, %2;" : "=f"(f.x), "=f"(f.y) : "l"(v));
    return f.x + f.y;
}
__device__ __forceinline__ float sigf(float x) { return 1.f / (1.f + expf(-x)); }

// ---- activation chunk staging: 64 rows x 128 k, swizzled float2 pairs ------
// hs[p*64 + (row ^ (p>>1))], pair p covers k = 2p, 2p+1
__device__ __forceinline__ void loadH(float4 r[8], const float* src, int stride, int k0, int tid) {
#pragma unroll
    for (int i = 0; i < 8; i++) {
        int q = tid + i * 256;
        int row = q >> 5, kq = q & 31;
        r[i] = __ldg((const float4*)(src + (size_t)row * stride + k0 + kq * 4));
    }
}
__device__ __forceinline__ void stsH(float2* hs, const float4 r[8], int tid) {
#pragma unroll
    for (int i = 0; i < 8; i++) {
        int q = tid + i * 256;
        int row = q >> 5, kq = q & 31;
        int sw = row ^ kq;
        hs[(2 * kq) * 64 + sw]     = make_float2(r[i].x, r[i].y);
        hs[(2 * kq + 1) * 64 + sw] = make_float2(r[i].z, r[i].w);
    }
}

// ---- weight chunk staging: NW rows x 128 k ----
template<int NI>
__device__ __forceinline__ void loadWg(float4 r[NI], const float* W, int K, int cBase, int k0, int tid) {
#pragma unroll
    for (int i = 0; i < NI; i++) {
        int q = tid + i * 256;
        int e = q >> 5, kq = q & 31;
        int gRow = (e >> 3) * MM + cBase + (e & 7);
        r[i] = __ldg((const float4*)(W + (size_t)gRow * K + k0 + kq * 4));
    }
}
template<int NI>
__device__ __forceinline__ void loadWf(float4 r[NI], const float* W, int K, int cBase, int k0, int tid) {
#pragma unroll
    for (int i = 0; i < NI; i++) {
        int q = tid + i * 256;
        int e = q >> 5, kq = q & 31;
        r[i] = __ldg((const float4*)(W + (size_t)(cBase + e) * K + k0 + kq * 4));
    }
}
template<int NI>
__device__ __forceinline__ void stsW(float* wc, const float4 r[NI], int tid) {
#pragma unroll
    for (int i = 0; i < NI; i++) {
        int q = tid + i * 256;
        int e = q >> 5, kq = q & 31;
        *(float4*)&wc[e * 128 + kq * 4] = r[i];
    }
}

// ---- chunk compute: GRU (6 outputs: 3 gates x 2 cols) ----
__device__ __forceinline__ void gruAcc(const float2* hs, const float* w,
                                       int row, int cg, ull acc[6]) {
#pragma unroll 8
    for (int i = 0; i < 32; i++) {
        int sw = row ^ i;
        ull h0 = *(const ull*)&hs[(2 * i) * 64 + sw];
        ull h1 = *(const ull*)&hs[(2 * i + 1) * 64 + sw];
#pragma unroll
        for (int g = 0; g < 3; g++)
#pragma unroll
            for (int j = 0; j < 2; j++) {
                ulonglong2 wv = *(const ulonglong2*)&w[(size_t)(g * 8 + cg * 2 + j) * 128 + i * 4];
                fma2(acc[g * 2 + j], h0, wv.x);
                fma2(acc[g * 2 + j], h1, wv.y);
            }
    }
}
// ---- chunk compute: FC ----
template<int NO>
__device__ __forceinline__ void fcAcc(const float2* hs, const float* wc, int row, int cg, ull* acc) {
#pragma unroll 8
    for (int i = 0; i < 32; i++) {
        int sw = row ^ i;
        ull h0 = *(const ull*)&hs[(2 * i) * 64 + sw];
        ull h1 = *(const ull*)&hs[(2 * i + 1) * 64 + sw];
#pragma unroll
        for (int j = 0; j < NO; j++) {
            ulonglong2 wv = *(const ulonglong2*)&wc[(cg * NO + j) * 128 + i * 4];
            fma2(acc[j], h0, wv.x);
            fma2(acc[j], h1, wv.y);
        }
    }
}

// ---------------- encoder GRU step (gi precomputed, streamed weights) -------
// grid 128 x 256. Block owns 8 n-cols (24 gate rows).
__global__ void __launch_bounds__(256) enc_step(
    const float* __restrict__ Whh, const float* __restrict__ bhh,
    const float* __restrict__ gi_t,
    const float* __restrict__ hin, float* __restrict__ hout,
    float* __restrict__ seq)
{
    extern __shared__ float sm[];
    float* wcA = sm;
    float* wcB = sm + 24 * 128;
    float2* hsA = (float2*)(sm + 2 * 24 * 128);
    float2* hsB = hsA + 4096;
    int tid = threadIdx.x, row = tid & 63, cg = tid >> 6;
    int cBase = blockIdx.x * 8;

    ull acc[6];
#pragma unroll
    for (int a = 0; a < 6; a++) acc[a] = 0ull;

    float4 sh[8]; float4 swr[3];
    loadH(sh, hin, MM, 0, tid);
    loadWg<3>(swr, Whh, MM, cBase, 0, tid);
    stsH(hsA, sh, tid); stsW<3>(wcA, swr, tid);
    __syncthreads();
    float2* curH = hsA; float2* nxtH = hsB;
    float* curW = wcA; float* nxtW = wcB;
#pragma unroll 1
    for (int ch = 0; ch < 8; ch++) {
        if (ch < 7) {
            loadH(sh, hin, MM, (ch + 1) * 128, tid);
            loadWg<3>(swr, Whh, MM, cBase, (ch + 1) * 128, tid);
        }
        gruAcc(curH, curW, row, cg, acc);
        if (ch < 7) { stsH(nxtH, sh, tid); stsW<3>(nxtW, swr, tid); }
        __syncthreads();
        float2* t1 = curH; curH = nxtH; nxtH = t1;
        float* t2 = curW; curW = nxtW; nxtW = t2;
    }

    int c = cBase + cg * 2;
    float2 br = *(const float2*)(bhh + c);
    float2 bz = *(const float2*)(bhh + MM + c);
    float2 bn = *(const float2*)(bhh + 2 * MM + c);
    const float* gi = gi_t + (size_t)row * G3;
    float2 gr = *(const float2*)(gi + c);
    float2 gz = *(const float2*)(gi + MM + c);
    float2 gn = *(const float2*)(gi + 2 * MM + c);
    float2 hp = __ldg((const float2*)(hin + (size_t)row * MM + c));
    float r0 = sigf(gr.x + rsum(acc[0]) + br.x);
    float r1 = sigf(gr.y + rsum(acc[1]) + br.y);
    float z0 = sigf(gz.x + rsum(acc[2]) + bz.x);
    float z1 = sigf(gz.y + rsum(acc[3]) + bz.y);
    float n0 = tanhf(gn.x + r0 * (rsum(acc[4]) + bn.x));
    float n1 = tanhf(gn.y + r1 * (rsum(acc[5]) + bn.y));
    float2 ho = {(1.f - z0) * n0 + z0 * hp.x, (1.f - z1) * n1 + z1 * hp.y};
    *(float2*)(hout + (size_t)row * MM + c) = ho;
    if (seq) *(float2*)(seq + (size_t)row * MM + c) = ho;
}

// ---------------- decoder GRU step (input + hidden, streamed weights) -------
__global__ void __launch_bounds__(256) gru_dec(
    const float* __restrict__ x, int Kx,
    const float* __restrict__ hin, float* __restrict__ hout,
    const float* __restrict__ Wih, const float* __restrict__ bih,
    const float* __restrict__ Whh, const float* __restrict__ bhh)
{
    extern __shared__ float sm[];
    float* wcA = sm;
    float* wcB = sm + 24 * 128;
    float2* hsA = (float2*)(sm + 2 * 24 * 128);
    float2* hsB = hsA + 4096;
    int tid = threadIdx.x, row = tid & 63, cg = tid >> 6;
    int cBase = blockIdx.x * 8;
    int xc = Kx / 128, NC = xc + 8;

    ull accA[6], accB[6];
#pragma unroll
    for (int a = 0; a < 6; a++) { accA[a] = 0ull; accB[a] = 0ull; }

    float4 sh[8]; float4 swr[3];
    loadH(sh, x, Kx, 0, tid);
    loadWg<3>(swr, Wih, Kx, cBase, 0, tid);
    stsH(hsA, sh, tid); stsW<3>(wcA, swr, tid);
    __syncthreads();
    float2* curH = hsA; float2* nxtH = hsB;
    float* curW = wcA; float* nxtW = wcB;
#pragma unroll 1
    for (int ch = 0; ch < NC; ch++) {
        if (ch + 1 < NC) {
            int nc = ch + 1;
            if (nc < xc) {
                loadH(sh, x, Kx, nc * 128, tid);
                loadWg<3>(swr, Wih, Kx, cBase, nc * 128, tid);
            } else {
                loadH(sh, hin, MM, (nc - xc) * 128, tid);
                loadWg<3>(swr, Whh, MM, cBase, (nc - xc) * 128, tid);
            }
        }
        if (ch < xc) gruAcc(curH, curW, row, cg, accA);
        else         gruAcc(curH, curW, row, cg, accB);
        if (ch + 1 < NC) { stsH(nxtH, sh, tid); stsW<3>(nxtW, swr, tid); }
        __syncthreads();
        float2* t1 = curH; curH = nxtH; nxtH = t1;
        float* t2 = curW; curW = nxtW; nxtW = t2;
    }

    int c = cBase + cg * 2;
    float2 bri = *(const float2*)(bih + c);
    float2 bzi = *(const float2*)(bih + MM + c);
    float2 bni = *(const float2*)(bih + 2 * MM + c);
    float2 brh = *(const float2*)(bhh + c);
    float2 bzh = *(const float2*)(bhh + MM + c);
    float2 bnh = *(const float2*)(bhh + 2 * MM + c);
    float2 hp = __ldg((const float2*)(hin + (size_t)row * MM + c));
    float r0 = sigf(rsum(accA[0]) + bri.x + rsum(accB[0]) + brh.x);
    float r1 = sigf(rsum(accA[1]) + bri.y + rsum(accB[1]) + brh.y);
    float z0 = sigf(rsum(accA[2]) + bzi.x + rsum(accB[2]) + bzh.x);
    float z1 = sigf(rsum(accA[3]) + bzi.y + rsum(accB[3]) + bzh.y);
    float n0 = tanhf(rsum(accA[4]) + bni.x + r0 * (rsum(accB[4]) + bnh.x));
    float n1 = tanhf(rsum(accA[5]) + bni.y + r1 * (rsum(accB[5]) + bnh.y));
    float2 ho = {(1.f - z0) * n0 + z0 * hp.x, (1.f - z1) * n1 + z1 * hp.y};
    *(float2*)(hout + (size_t)row * MM + c) = ho;
}

// ---------------- fc1: zpre = h1 @ fc1_w^T + b ----------------
__global__ void __launch_bounds__(256) fc1_k(
    const float* __restrict__ A, const float* __restrict__ W,
    const float* __restrict__ bias, float* __restrict__ C)
{
    extern __shared__ float sm[];
    float* wcA = sm; float* wcB = sm + 16 * 128;
    float2* hsA = (float2*)(sm + 2 * 16 * 128);
    float2* hsB = hsA + 4096;
    int tid = threadIdx.x, row = tid & 63, cg = tid >> 6;
    int cBase = blockIdx.x * 16;
    ull acc[4] = {0ull, 0ull, 0ull, 0ull};

    float4 sh[8]; float4 swr[2];
    loadH(sh, A, MM, 0, tid);
    loadWf<2>(swr, W, MM, cBase, 0, tid);
    stsH(hsA, sh, tid); stsW<2>(wcA, swr, tid);
    __syncthreads();
    float2* curH = hsA; float2* nxtH = hsB;
    float* curW = wcA; float* nxtW = wcB;
#pragma unroll 1
    for (int ch = 0; ch < 8; ch++) {
        if (ch < 7) {
            loadH(sh, A, MM, (ch + 1) * 128, tid);
            loadWf<2>(swr, W, MM, cBase, (ch + 1) * 128, tid);
        }
        fcAcc<4>(curH, curW, row, cg, acc);
        if (ch < 7) { stsH(nxtH, sh, tid); stsW<2>(nxtW, swr, tid); }
        __syncthreads();
        float2* t1 = curH; curH = nxtH; nxtH = t1;
        float* t2 = curW; curW = nxtW; nxtW = t2;
    }
    int c = cBase + cg * 4;
    float4 bv = *(const float4*)(bias + c);
    float4 o = {rsum(acc[0]) + bv.x, rsum(acc[1]) + bv.y,
                rsum(acc[2]) + bv.z, rsum(acc[3]) + bv.w};
    *(float4*)(C + (size_t)row * LMM + c) = o;
}

// ---------------- fc2: logits ----------------
__global__ void __launch_bounds__(256) fc2_k(
    const float* __restrict__ A, const float* __restrict__ W,
    const float* __restrict__ bias, float* __restrict__ out, int s)
{
    extern __shared__ float sm[];
    float* wcA = sm; float* wcB = sm + 8 * 128;
    float2* hsA = (float2*)(sm + 2 * 8 * 128);
    float2* hsB = hsA + 4096;
    int tid = threadIdx.x, row = tid & 63, cg = tid >> 6;
    int cBase = blockIdx.x * 8;
    ull acc[2] = {0ull, 0ull};

    float4 sh[8]; float4 swr[1];
    loadH(sh, A, LMM, 0, tid);
    loadWf<1>(swr, W, LMM, cBase, 0, tid);
    stsH(hsA, sh, tid); stsW<1>(wcA, swr, tid);
    __syncthreads();
    float2* curH = hsA; float2* nxtH = hsB;
    float* curW = wcA; float* nxtW = wcB;
#pragma unroll 1
    for (int ch = 0; ch < 16; ch++) {
        if (ch < 15) {
            loadH(sh, A, LMM, (ch + 1) * 128, tid);
            loadWf<1>(swr, W, LMM, cBase, (ch + 1) * 128, tid);
        }
        fcAcc<2>(curH, curW, row, cg, acc);
        if (ch < 15) { stsH(nxtH, sh, tid); stsW<1>(nxtW, swr, tid); }
        __syncthreads();
        float2* t1 = curH; curH = nxtH; nxtH = t1;
        float* t2 = curW; curW = nxtW; nxtW = t2;
    }
    int c = cBase + cg * 2;
    float2 bv = *(const float2*)(bias + c);
    float2 o = {rsum(acc[0]) + bv.x, rsum(acc[1]) + bv.y};
    *(float2*)(g_logits + (size_t)row * OO + c) = o;
    *(float2*)(out + ((size_t)row * TDEC + s) * OO + c) = o;
}

// ---------------- softmax feedback ----------------
__global__ void __launch_bounds__(512) softmax_k(float* __restrict__ y_out) {
    int b = blockIdx.x, o = threadIdx.x;
    float v = g_logits[(size_t)b * OO + o];
    __shared__ float red[16];
    __shared__ float bc;
    int w = o >> 5, l = o & 31;
    float m = v;
#pragma unroll
    for (int d = 16; d; d >>= 1) m = fmaxf(m, __shfl_down_sync(0xffffffffu, m, d));
    if (l == 0) red[w] = m;
    __syncthreads();
    if (o == 0) {
        float a = red[0];
        for (int i = 1; i < 16; i++) a = fmaxf(a, red[i]);
        bc = a;
    }
    __syncthreads();
    float e = expf(v - bc);
    float sum = e;
#pragma unroll
    for (int d = 16; d; d >>= 1) sum += __shfl_down_sync(0xffffffffu, sum, d);
    if (l == 0) red[w] = sum;
    __syncthreads();
    if (o == 0) {
        float a = 0.f;
        for (int i = 0; i < 16; i++) a += red[i];
        bc = a;
    }
    __syncthreads();
    y_out[(size_t)b * OO + o] = e / bc;
}

// ---------------- LayerNorm + exact GELU ----------------
__global__ void __launch_bounds__(256) ln_gelu_kernel(
    const float* __restrict__ zpre, float* __restrict__ z,
    const float* __restrict__ g, const float* __restrict__ bta)
{
    int b = blockIdx.x, tid = threadIdx.x;
    float v[8];
    float s = 0.f, s2 = 0.f;
#pragma unroll
    for (int j = 0; j < 8; j++) {
        float t = zpre[(size_t)b * LMM + tid + j * 256];
        v[j] = t; s += t; s2 += t * t;
    }
    __shared__ float red[64];
#pragma unroll
    for (int o = 16; o; o >>= 1) {
        s += __shfl_down_sync(0xffffffffu, s, o);
        s2 += __shfl_down_sync(0xffffffffu, s2, o);
    }
    int w = tid >> 5, l = tid & 31;
    if (l == 0) { red[w] = s; red[32 + w] = s2; }
    __syncthreads();
    if (tid == 0) {
        float a = 0.f, a2 = 0.f;
        for (int i = 0; i < 8; i++) { a += red[i]; a2 += red[32 + i]; }
        red[0] = a; red[32] = a2;
    }
    __syncthreads();
    float mu = red[0] * (1.f / (float)LMM);
    float var = red[32] * (1.f / (float)LMM) - mu * mu;
    float rs = rsqrtf(var + 1e-5f);
#pragma unroll
    for (int j = 0; j < 8; j++) {
        int c = tid + j * 256;
        float t = (v[j] - mu) * rs * g[c] + bta[c];
        z[(size_t)b * LMM + c] = t * normcdff(t);
    }
}

// ---------------- init / transpose / big GEMM ------------
__global__ void zero_init_kernel() {
    int i = blockIdx.x * blockDim.x + threadIdx.x;
    int stride = gridDim.x * blockDim.x;
    for (; i < BB * MM; i += stride) { g_e0A[i] = 0.f; g_e1A[i] = 0.f; }
}
__global__ void copy_y_kernel(const float* __restrict__ Y0) {
    int i = blockIdx.x * blockDim.x + threadIdx.x;
    if (i < BB * OO) g_yA[i] = Y0[i];
}
__global__ void transpose_x_kernel(const float* __restrict__ X) {
    int i = blockIdx.x * blockDim.x + threadIdx.x;
    int stride = gridDim.x * blockDim.x;
    const int total = TIN * BB * NIN;
    for (; i < total; i += stride) {
        int n = i % NIN;
        int r = i / NIN;
        int t = r / BB, b = r % BB;
        g_xt[i] = X[(b * TIN + t) * NIN + n];
    }
}

__global__ void __launch_bounds__(256) gemm_big_kernel(
    const float* __restrict__ A, const float* __restrict__ W,
    const float* __restrict__ bias, float* __restrict__ C,
    int K, int Cn)
{
    __shared__ __align__(16) float As[16][132];
    __shared__ __align__(16) float Bs[16][132];
    int tid = threadIdx.x;
    int tx = tid & 15, ty = tid >> 4;
    int r0 = blockIdx.y * 128, c0 = blockIdx.x * 128;
    ull acc[8][4];
#pragma unroll
    for (int i = 0; i < 8; i++)
#pragma unroll
        for (int j = 0; j < 4; j++) acc[i][j] = 0ull;
    for (int k0 = 0; k0 < K; k0 += 16) {
#pragma unroll
        for (int i = 0; i < 2; i++) {
            int q = tid + i * 256;
            int rr = q >> 2, kq = q & 3;
            float4 v = *(const float4*)(A + (size_t)(r0 + rr) * K + k0 + kq * 4);
            As[kq * 4 + 0][rr] = v.x; As[kq * 4 + 1][rr] = v.y;
            As[kq * 4 + 2][rr] = v.z; As[kq * 4 + 3][rr] = v.w;
        }
#pragma unroll
        for (int i = 0; i < 2; i++) {
            int q = tid + i * 256;
            int wn = q >> 2, kq = q & 3;
            float4 v = *(const float4*)(W + (size_t)(c0 + wn) * K + k0 + kq * 4);
            Bs[kq * 4 + 0][wn] = v.x; Bs[kq * 4 + 1][wn] = v.y;
            Bs[kq * 4 + 2][wn] = v.z; Bs[kq * 4 + 3][wn] = v.w;
        }
        __syncthreads();
#pragma unroll
        for (int kk = 0; kk < 16; kk++) {
            ulonglong2 bq0 = *(ulonglong2*)&Bs[kk][tx * 8];
            ulonglong2 bq1 = *(ulonglong2*)&Bs[kk][tx * 8 + 4];
            ull bp[4] = {bq0.x, bq0.y, bq1.x, bq1.y};
            float4 a0 = *(float4*)&As[kk][ty * 8];
            float4 a1 = *(float4*)&As[kk][ty * 8 + 4];
            float av[8] = {a0.x, a0.y, a0.z, a0.w, a1.x, a1.y, a1.z, a1.w};
#pragma unroll
            for (int i = 0; i < 8; i++) {
                ull ap;
                asm("mov.b64 %0, {%1,%1};" : "=l"(ap) : "f"(av[i]));
#pragma unroll
                for (int j = 0; j < 4; j++) fma2(acc[i][j], ap, bp[j]);
            }
        }
        __syncthreads();
    }
    int c = c0 + tx * 8;
    float4 bv0 = *(const float4*)(bias + c);
    float4 bv1 = *(const float4*)(bias + c + 4);
#pragma unroll
    for (int i = 0; i < 8; i++) {
        int r = r0 + ty * 8 + i;
        float2 p0, p1, p2, p3;
        asm("mov.b64 {%0,%1}, %2;" : "=f"(p0.x), "=f"(p0.y) : "l"(acc[i][0]));
        asm("mov.b64 {%0,%1}, %2;" : "=f"(p1.x), "=f"(p1.y) : "l"(acc[i][1]));
        asm("mov.b64 {%0,%1}, %2;" : "=f"(p2.x), "=f"(p2.y) : "l"(acc[i][2]));
        asm("mov.b64 {%0,%1}, %2;" : "=f"(p3.x), "=f"(p3.y) : "l"(acc[i][3]));
        float4 o0 = {p0.x + bv0.x, p0.y + bv0.y, p1.x + bv0.z, p1.y + bv0.w};
        float4 o1 = {p2.x + bv1.x, p2.y + bv1.y, p3.x + bv1.z, p3.y + bv1.w};
        *(float4*)(C + (size_t)r * Cn + c) = o0;
        *(float4*)(C + (size_t)r * Cn + c + 4) = o1;
    }
}

// ---------------- host launch ----------------
#define GRU_SM ((2 * 24 * 128 + 2 * 8192) * 4)
#define FC1_SM ((2 * 16 * 128 + 2 * 8192) * 4)
#define FC2_SM ((2 * 8 * 128 + 2 * 8192) * 4)

extern "C" void kernel_launch(void* const* d_in, const int* in_sizes, int n_in,
                              void* d_out, int out_size)
{
    const float* X        = (const float*)d_in[0];
    const float* Y0       = (const float*)d_in[1];
    const float* enc_Wih0 = (const float*)d_in[2];
    const float* enc_Whh0 = (const float*)d_in[3];
    const float* enc_bih0 = (const float*)d_in[4];
    const float* enc_bhh0 = (const float*)d_in[5];
    const float* enc_Wih1 = (const float*)d_in[6];
    const float* enc_Whh1 = (const float*)d_in[7];
    const float* enc_bih1 = (const float*)d_in[8];
    const float* enc_bhh1 = (const float*)d_in[9];
    const float* dec_Wih0 = (const float*)d_in[10];
    const float* dec_Whh0 = (const float*)d_in[11];
    const float* dec_bih0 = (const float*)d_in[12];
    const float* dec_bhh0 = (const float*)d_in[13];
    const float* dec_Wih1 = (const float*)d_in[14];
    const float* dec_Whh1 = (const float*)d_in[15];
    const float* dec_bih1 = (const float*)d_in[16];
    const float* dec_bhh1 = (const float*)d_in[17];
    const float* fc1_w    = (const float*)d_in[18];
    const float* fc1_b    = (const float*)d_in[19];
    const float* ln_g     = (const float*)d_in[20];
    const float* ln_b     = (const float*)d_in[21];
    const float* fc2_w    = (const float*)d_in[22];
    const float* fc2_b    = (const float*)d_in[23];
    float* out = (float*)d_out;

    float *xt, *gi, *seq0, *e0A, *e0B, *e1A, *e1B, *yA, *yB, *zpre, *z;
    cudaGetSymbolAddress((void**)&xt,   g_xt);
    cudaGetSymbolAddress((void**)&gi,   g_gi);
    cudaGetSymbolAddress((void**)&seq0, g_seq0);
    cudaGetSymbolAddress((void**)&e0A,  g_e0A);
    cudaGetSymbolAddress((void**)&e0B,  g_e0B);
    cudaGetSymbolAddress((void**)&e1A,  g_e1A);
    cudaGetSymbolAddress((void**)&e1B,  g_e1B);
    cudaGetSymbolAddress((void**)&yA,   g_yA);
    cudaGetSymbolAddress((void**)&yB,   g_yB);
    cudaGetSymbolAddress((void**)&zpre, g_zpre);
    cudaGetSymbolAddress((void**)&z,    g_z);

    cudaFuncSetAttribute(enc_step, cudaFuncAttributeMaxDynamicSharedMemorySize, GRU_SM);
    cudaFuncSetAttribute(gru_dec,  cudaFuncAttributeMaxDynamicSharedMemorySize, GRU_SM);
    cudaFuncSetAttribute(fc1_k,    cudaFuncAttributeMaxDynamicSharedMemorySize, FC1_SM);
    cudaFuncSetAttribute(fc2_k,    cudaFuncAttributeMaxDynamicSharedMemorySize, FC2_SM);

    zero_init_kernel<<<256, 256>>>();
    copy_y_kernel<<<(BB * OO + 255) / 256, 256>>>(Y0);
    transpose_x_kernel<<<2048, 256>>>(X);

    const int R = TIN * BB;

    // encoder layer 0
    gemm_big_kernel<<<dim3(G3 / 128, R / 128), 256>>>(xt, enc_Wih0, enc_bih0, gi, NIN, G3);
    for (int t = 0; t < TIN; t++) {
        const float* hi = (t & 1) ? e0B : e0A;
        float* ho       = (t & 1) ? e0A : e0B;
        enc_step<<<128, 256, GRU_SM>>>(enc_Whh0, enc_bhh0,
                                       gi + (size_t)t * BB * G3,
                                       hi, ho, seq0 + (size_t)t * BB * MM);
    }

    // encoder layer 1
    gemm_big_kernel<<<dim3(G3 / 128, R / 128), 256>>>(seq0, enc_Wih1, enc_bih1, gi, MM, G3);
    for (int t = 0; t < TIN; t++) {
        const float* hi = (t & 1) ? e1B : e1A;
        float* ho       = (t & 1) ? e1A : e1B;
        enc_step<<<128, 256, GRU_SM>>>(enc_Whh1, enc_bhh1,
                                       gi + (size_t)t * BB * G3,
                                       hi, ho, nullptr);
    }

    // decoder
    for (int s = 0; s < TDEC; s++) {
        const float* yin = (s & 1) ? yB : yA;
        float* yout      = (s & 1) ? yA : yB;
        const float* h0i = (s & 1) ? e0B : e0A;
        float* h0o       = (s & 1) ? e0A : e0B;
        const float* h1i = (s & 1) ? e1B : e1A;
        float* h1o       = (s & 1) ? e1A : e1B;

        gru_dec<<<128, 256, GRU_SM>>>(yin, OO, h0i, h0o, dec_Wih0, dec_bih0, dec_Whh0, dec_bhh0);
        gru_dec<<<128, 256, GRU_SM>>>(h0o, MM, h1i, h1o, dec_Wih1, dec_bih1, dec_Whh1, dec_bhh1);
        fc1_k<<<128, 256, FC1_SM>>>(h1o, fc1_w, fc1_b, zpre);
        ln_gelu_kernel<<<BB, 256>>>(zpre, z, ln_g, ln_b);
        fc2_k<<<64, 256, FC2_SM>>>(z, fc2_w, fc2_b, out, s);
        softmax_k<<<BB, 512>>>(yout);
    }
}

// round 11
// speedup vs baseline: 1.9588x; 1.0440x over previous
#include <cuda_runtime.h>
#include <math.h>

#define BB   64
#define TIN  128
#define NIN  256
#define MM   1024
#define OO   512
#define LMM  2048
#define TDEC 64
#define G3   3072
typedef unsigned long long ull;

// ---------------- scratch ----------------
__device__ float g_xt[TIN * BB * NIN];
__device__ float g_gi[TIN * BB * G3];
__device__ float g_seq0[TIN * BB * MM];
__device__ float g_e0A[BB * MM], g_e0B[BB * MM];
__device__ float g_e1A[BB * MM], g_e1B[BB * MM];
__device__ float g_yA[BB * OO], g_yB[BB * OO];
__device__ float g_zpre[BB * LMM];
__device__ float g_z[BB * LMM];
__device__ float g_logits[BB * OO];
__device__ unsigned g_barc, g_barg;

// ---------------- helpers ----------------
__device__ __forceinline__ void fma2(ull& d, ull a, ull b) {
    asm("fma.rn.f32x2 %0, %1, %2, %0;" : "+l"(d) : "l"(a), "l"(b));
}
__device__ __forceinline__ float rsum(ull v) {
    float2 f;
    asm("mov.b64 {%0,%1}, %2;" : "=f"(f.x), "=f"(f.y) : "l"(v));
    return f.x + f.y;
}
__device__ __forceinline__ float sigf(float x) { return 1.f / (1.f + expf(-x)); }

// device-wide barrier; co-residency guaranteed by cooperative launch
__device__ __forceinline__ void gbar() {
    __syncthreads();
    __threadfence();
    if (threadIdx.x == 0) {
        unsigned gen = ((volatile unsigned*)&g_barg)[0];
        if (atomicAdd(&g_barc, 1u) == gridDim.x - 1) {
            g_barc = 0;
            __threadfence();
            atomicAdd(&g_barg, 1u);
        } else {
            while (((volatile unsigned*)&g_barg)[0] == gen) {}
        }
    }
    __syncthreads();
}

// ---- activation chunk staging: 64 rows x 128 k, swizzled float2 pairs ------
template<bool CG>
__device__ __forceinline__ void loadH(float4 r[8], const float* src, int stride, int k0, int tid) {
#pragma unroll
    for (int i = 0; i < 8; i++) {
        int q = tid + i * 256;
        int row = q >> 5, kq = q & 31;
        const float4* p = (const float4*)(src + (size_t)row * stride + k0 + kq * 4);
        r[i] = CG ? __ldcg(p) : __ldg(p);
    }
}
__device__ __forceinline__ void stsH(float2* hs, const float4 r[8], int tid) {
#pragma unroll
    for (int i = 0; i < 8; i++) {
        int q = tid + i * 256;
        int row = q >> 5, kq = q & 31;
        int sw = row ^ kq;
        hs[(2 * kq) * 64 + sw]     = make_float2(r[i].x, r[i].y);
        hs[(2 * kq + 1) * 64 + sw] = make_float2(r[i].z, r[i].w);
    }
}

// ---- weight chunk staging ----
template<int NI>
__device__ __forceinline__ void loadWg(float4 r[NI], const float* W, int K, int cBase, int k0, int tid) {
#pragma unroll
    for (int i = 0; i < NI; i++) {
        int q = tid + i * 256;
        int e = q >> 5, kq = q & 31;
        int gRow = (e >> 3) * MM + cBase + (e & 7);
        r[i] = __ldg((const float4*)(W + (size_t)gRow * K + k0 + kq * 4));
    }
}
template<int NI>
__device__ __forceinline__ void loadWf(float4 r[NI], const float* W, int K, int cBase, int k0, int tid) {
#pragma unroll
    for (int i = 0; i < NI; i++) {
        int q = tid + i * 256;
        int e = q >> 5, kq = q & 31;
        r[i] = __ldg((const float4*)(W + (size_t)(cBase + e) * K + k0 + kq * 4));
    }
}
template<int NI>
__device__ __forceinline__ void stsW(float* wc, const float4 r[NI], int tid) {
#pragma unroll
    for (int i = 0; i < NI; i++) {
        int q = tid + i * 256;
        int e = q >> 5, kq = q & 31;
        *(float4*)&wc[e * 128 + kq * 4] = r[i];
    }
}

// ---- chunk compute: GRU (stride-parameterized for resident weights) ----
__device__ __forceinline__ void gruAccS(const float2* hs, const float* w, int wstride, int kOff,
                                        int row, int cg, ull acc[6]) {
#pragma unroll 8
    for (int i = 0; i < 32; i++) {
        int sw = row ^ i;
        ull h0 = *(const ull*)&hs[(2 * i) * 64 + sw];
        ull h1 = *(const ull*)&hs[(2 * i + 1) * 64 + sw];
#pragma unroll
        for (int g = 0; g < 3; g++)
#pragma unroll
            for (int j = 0; j < 2; j++) {
                ulonglong2 wv = *(const ulonglong2*)&w[(size_t)(g * 8 + cg * 2 + j) * wstride + kOff + i * 4];
                fma2(acc[g * 2 + j], h0, wv.x);
                fma2(acc[g * 2 + j], h1, wv.y);
            }
    }
}
// ---- chunk compute: FC ----
template<int NO>
__device__ __forceinline__ void fcAcc(const float2* hs, const float* wc, int row, int cg, ull* acc) {
#pragma unroll 8
    for (int i = 0; i < 32; i++) {
        int sw = row ^ i;
        ull h0 = *(const ull*)&hs[(2 * i) * 64 + sw];
        ull h1 = *(const ull*)&hs[(2 * i + 1) * 64 + sw];
#pragma unroll
        for (int j = 0; j < NO; j++) {
            ulonglong2 wv = *(const ulonglong2*)&wc[(cg * NO + j) * 128 + i * 4];
            fma2(acc[j], h0, wv.x);
            fma2(acc[j], h1, wv.y);
        }
    }
}

// ============ persistent encoder layer (weights smem-resident) ==============
// cooperative launch: 128 blocks x 256 threads, 160KB dyn smem
__global__ void __launch_bounds__(256) enc_persist(
    const float* __restrict__ Whh, const float* __restrict__ bhh,
    const float* __restrict__ giB, float* hA, float* hB, float* seq)
{
    extern __shared__ float sm[];
    float* ws = sm;                              // 24 x 1024
    float2* hsA = (float2*)(sm + 24 * 1024);     // 4096 float2
    float2* hsB = hsA + 4096;
    int tid = threadIdx.x, row = tid & 63, cg = tid >> 6;
    int cBase = blockIdx.x * 8;
    int c = cBase + cg * 2;

#pragma unroll
    for (int i = 0; i < 24; i++) {
        int q = tid + i * 256;
        int e = q >> 8, kq = q & 255;
        int gRow = (e >> 3) * MM + cBase + (e & 7);
        *(float4*)&ws[e * 1024 + kq * 4] =
            __ldg((const float4*)(Whh + (size_t)gRow * MM + kq * 4));
    }
    float2 br = *(const float2*)(bhh + c);
    float2 bz = *(const float2*)(bhh + MM + c);
    float2 bn = *(const float2*)(bhh + 2 * MM + c);
    __syncthreads();

    for (int t = 0; t < TIN; t++) {
        const float* hin = (t & 1) ? hB : hA;
        float* hout      = (t & 1) ? hA : hB;
        ull acc[6];
#pragma unroll
        for (int a = 0; a < 6; a++) acc[a] = 0ull;

        float4 st[8];
        loadH<true>(st, hin, MM, 0, tid);
        stsH(hsA, st, tid);
        __syncthreads();
        float2* cur = hsA; float2* nxt = hsB;
#pragma unroll 1
        for (int ch = 0; ch < 8; ch++) {
            if (ch < 7) loadH<true>(st, hin, MM, (ch + 1) * 128, tid);
            gruAccS(cur, ws, 1024, ch * 128, row, cg, acc);
            if (ch < 7) stsH(nxt, st, tid);
            __syncthreads();
            float2* tmp = cur; cur = nxt; nxt = tmp;
        }

        const float* gi = giB + ((size_t)t * BB + row) * G3;
        float2 gr = *(const float2*)(gi + c);
        float2 gz = *(const float2*)(gi + MM + c);
        float2 gn = *(const float2*)(gi + 2 * MM + c);
        float2 hp = __ldcg((const float2*)(hin + (size_t)row * MM + c));
        float r0 = sigf(gr.x + rsum(acc[0]) + br.x);
        float r1 = sigf(gr.y + rsum(acc[1]) + br.y);
        float z0 = sigf(gz.x + rsum(acc[2]) + bz.x);
        float z1 = sigf(gz.y + rsum(acc[3]) + bz.y);
        float n0 = tanhf(gn.x + r0 * (rsum(acc[4]) + bn.x));
        float n1 = tanhf(gn.y + r1 * (rsum(acc[5]) + bn.y));
        float2 ho = {(1.f - z0) * n0 + z0 * hp.x, (1.f - z1) * n1 + z1 * hp.y};
        *(float2*)(hout + (size_t)row * MM + c) = ho;
        if (seq) *(float2*)(seq + ((size_t)t * BB + row) * MM + c) = ho;
        gbar();
    }
}

// ============ persistent decoder: all 64 steps, 6 phases/step ===============
__device__ __forceinline__ void phase_gru(
    const float* x, int Kx, const float* hin, float* hout,
    const float* Wih, const float* bih, const float* Whh, const float* bhh,
    float* sm, int tid, int row, int cg)
{
    float* wcA = sm; float* wcB = sm + 3072;
    float2* hsA = (float2*)(sm + 6144); float2* hsB = hsA + 4096;
    int cBase = blockIdx.x * 8;
    int xc = Kx / 128, NC = xc + 8;

    ull accA[6], accB[6];
#pragma unroll
    for (int a = 0; a < 6; a++) { accA[a] = 0ull; accB[a] = 0ull; }

    float4 sh[8]; float4 swr[3];
    loadH<true>(sh, x, Kx, 0, tid);
    loadWg<3>(swr, Wih, Kx, cBase, 0, tid);
    stsH(hsA, sh, tid); stsW<3>(wcA, swr, tid);
    __syncthreads();
    float2* curH = hsA; float2* nxtH = hsB;
    float* curW = wcA; float* nxtW = wcB;
#pragma unroll 1
    for (int ch = 0; ch < NC; ch++) {
        if (ch + 1 < NC) {
            int nc = ch + 1;
            if (nc < xc) {
                loadH<true>(sh, x, Kx, nc * 128, tid);
                loadWg<3>(swr, Wih, Kx, cBase, nc * 128, tid);
            } else {
                loadH<true>(sh, hin, MM, (nc - xc) * 128, tid);
                loadWg<3>(swr, Whh, MM, cBase, (nc - xc) * 128, tid);
            }
        }
        if (ch < xc) gruAccS(curH, curW, 128, 0, row, cg, accA);
        else         gruAccS(curH, curW, 128, 0, row, cg, accB);
        if (ch + 1 < NC) { stsH(nxtH, sh, tid); stsW<3>(nxtW, swr, tid); }
        __syncthreads();
        float2* t1 = curH; curH = nxtH; nxtH = t1;
        float* t2 = curW; curW = nxtW; nxtW = t2;
    }

    int c = cBase + cg * 2;
    float2 bri = *(const float2*)(bih + c);
    float2 bzi = *(const float2*)(bih + MM + c);
    float2 bni = *(const float2*)(bih + 2 * MM + c);
    float2 brh = *(const float2*)(bhh + c);
    float2 bzh = *(const float2*)(bhh + MM + c);
    float2 bnh = *(const float2*)(bhh + 2 * MM + c);
    float2 hp = __ldcg((const float2*)(hin + (size_t)row * MM + c));
    float r0 = sigf(rsum(accA[0]) + bri.x + rsum(accB[0]) + brh.x);
    float r1 = sigf(rsum(accA[1]) + bri.y + rsum(accB[1]) + brh.y);
    float z0 = sigf(rsum(accA[2]) + bzi.x + rsum(accB[2]) + bzh.x);
    float z1 = sigf(rsum(accA[3]) + bzi.y + rsum(accB[3]) + bzh.y);
    float n0 = tanhf(rsum(accA[4]) + bni.x + r0 * (rsum(accB[4]) + bnh.x));
    float n1 = tanhf(rsum(accA[5]) + bni.y + r1 * (rsum(accB[5]) + bnh.y));
    float2 ho = {(1.f - z0) * n0 + z0 * hp.x, (1.f - z1) * n1 + z1 * hp.y};
    *(float2*)(hout + (size_t)row * MM + c) = ho;
}

__device__ __forceinline__ void phase_fc1(
    const float* A, const float* W, const float* bias,
    float* sm, int tid, int row, int cg)
{
    float* wcA = sm; float* wcB = sm + 2048;
    float2* hsA = (float2*)(sm + 4096); float2* hsB = hsA + 4096;
    int cBase = blockIdx.x * 16;
    ull acc[4] = {0ull, 0ull, 0ull, 0ull};

    float4 sh[8]; float4 swr[2];
    loadH<true>(sh, A, MM, 0, tid);
    loadWf<2>(swr, W, MM, cBase, 0, tid);
    stsH(hsA, sh, tid); stsW<2>(wcA, swr, tid);
    __syncthreads();
    float2* curH = hsA; float2* nxtH = hsB;
    float* curW = wcA; float* nxtW = wcB;
#pragma unroll 1
    for (int ch = 0; ch < 8; ch++) {
        if (ch < 7) {
            loadH<true>(sh, A, MM, (ch + 1) * 128, tid);
            loadWf<2>(swr, W, MM, cBase, (ch + 1) * 128, tid);
        }
        fcAcc<4>(curH, curW, row, cg, acc);
        if (ch < 7) { stsH(nxtH, sh, tid); stsW<2>(nxtW, swr, tid); }
        __syncthreads();
        float2* t1 = curH; curH = nxtH; nxtH = t1;
        float* t2 = curW; curW = nxtW; nxtW = t2;
    }
    int c = cBase + cg * 4;
    float4 bv = *(const float4*)(bias + c);
    float4 o = {rsum(acc[0]) + bv.x, rsum(acc[1]) + bv.y,
                rsum(acc[2]) + bv.z, rsum(acc[3]) + bv.w};
    *(float4*)(g_zpre + (size_t)row * LMM + c) = o;
}

__device__ __forceinline__ void phase_ln(const float* g, const float* bta, int tid)
{
    int b = blockIdx.x;
    float v[8];
    float s = 0.f, s2 = 0.f;
#pragma unroll
    for (int j = 0; j < 8; j++) {
        float t = __ldcg(&g_zpre[(size_t)b * LMM + tid + j * 256]);
        v[j] = t; s += t; s2 += t * t;
    }
    __shared__ float red[64];
#pragma unroll
    for (int o = 16; o; o >>= 1) {
        s += __shfl_down_sync(0xffffffffu, s, o);
        s2 += __shfl_down_sync(0xffffffffu, s2, o);
    }
    int w = tid >> 5, l = tid & 31;
    if (l == 0) { red[w] = s; red[32 + w] = s2; }
    __syncthreads();
    if (tid == 0) {
        float a = 0.f, a2 = 0.f;
        for (int i = 0; i < 8; i++) { a += red[i]; a2 += red[32 + i]; }
        red[0] = a; red[32] = a2;
    }
    __syncthreads();
    float mu = red[0] * (1.f / (float)LMM);
    float var = red[32] * (1.f / (float)LMM) - mu * mu;
    float rs = rsqrtf(var + 1e-5f);
#pragma unroll
    for (int j = 0; j < 8; j++) {
        int cc = tid + j * 256;
        float t = (v[j] - mu) * rs * g[cc] + bta[cc];
        g_z[(size_t)b * LMM + cc] = t * normcdff(t);
    }
}

__device__ __forceinline__ void phase_fc2(
    const float* W, const float* bias, float* out, int s,
    float* sm, int tid, int row, int cg)
{
    float* wcA = sm; float* wcB = sm + 1024;
    float2* hsA = (float2*)(sm + 2048); float2* hsB = hsA + 4096;
    int cBase = blockIdx.x * 8;
    ull acc[2] = {0ull, 0ull};

    float4 sh[8]; float4 swr[1];
    loadH<true>(sh, g_z, LMM, 0, tid);
    loadWf<1>(swr, W, LMM, cBase, 0, tid);
    stsH(hsA, sh, tid); stsW<1>(wcA, swr, tid);
    __syncthreads();
    float2* curH = hsA; float2* nxtH = hsB;
    float* curW = wcA; float* nxtW = wcB;
#pragma unroll 1
    for (int ch = 0; ch < 16; ch++) {
        if (ch < 15) {
            loadH<true>(sh, g_z, LMM, (ch + 1) * 128, tid);
            loadWf<1>(swr, W, LMM, cBase, (ch + 1) * 128, tid);
        }
        fcAcc<2>(curH, curW, row, cg, acc);
        if (ch < 15) { stsH(nxtH, sh, tid); stsW<1>(nxtW, swr, tid); }
        __syncthreads();
        float2* t1 = curH; curH = nxtH; nxtH = t1;
        float* t2 = curW; curW = nxtW; nxtW = t2;
    }
    int c = cBase + cg * 2;
    float2 bv = *(const float2*)(bias + c);
    float2 o = {rsum(acc[0]) + bv.x, rsum(acc[1]) + bv.y};
    *(float2*)(g_logits + (size_t)row * OO + c) = o;
    *(float2*)(out + ((size_t)row * TDEC + s) * OO + c) = o;
}

__device__ __forceinline__ void phase_softmax(float* yout, int tid)
{
    int b = blockIdx.x;
    float v0 = __ldcg(&g_logits[(size_t)b * OO + tid]);
    float v1 = __ldcg(&g_logits[(size_t)b * OO + 256 + tid]);
    __shared__ float sred[9];
    int w = tid >> 5, l = tid & 31;
    float m = fmaxf(v0, v1);
#pragma unroll
    for (int d = 16; d; d >>= 1) m = fmaxf(m, __shfl_down_sync(0xffffffffu, m, d));
    if (l == 0) sred[w] = m;
    __syncthreads();
    if (tid == 0) {
        float a = sred[0];
        for (int i = 1; i < 8; i++) a = fmaxf(a, sred[i]);
        sred[8] = a;
    }
    __syncthreads();
    float mx = sred[8];
    float e0 = expf(v0 - mx), e1 = expf(v1 - mx);
    float su = e0 + e1;
#pragma unroll
    for (int d = 16; d; d >>= 1) su += __shfl_down_sync(0xffffffffu, su, d);
    __syncthreads();
    if (l == 0) sred[w] = su;
    __syncthreads();
    if (tid == 0) {
        float a = 0.f;
        for (int i = 0; i < 8; i++) a += sred[i];
        sred[8] = a;
    }
    __syncthreads();
    float inv = 1.f / sred[8];
    yout[(size_t)b * OO + tid]       = e0 * inv;
    yout[(size_t)b * OO + 256 + tid] = e1 * inv;
}

__global__ void __launch_bounds__(256) dec_persist(
    float* __restrict__ out,
    float* yA, float* yB, float* h0A, float* h0B, float* h1A, float* h1B,
    const float* __restrict__ Wih0, const float* __restrict__ bih0,
    const float* __restrict__ Whh0, const float* __restrict__ bhh0,
    const float* __restrict__ Wih1, const float* __restrict__ bih1,
    const float* __restrict__ Whh1, const float* __restrict__ bhh1,
    const float* __restrict__ fc1w, const float* __restrict__ fc1b,
    const float* __restrict__ lng, const float* __restrict__ lnb,
    const float* __restrict__ fc2w, const float* __restrict__ fc2b)
{
    extern __shared__ float sm[];
    int tid = threadIdx.x, row = tid & 63, cg = tid >> 6;

    for (int s = 0; s < TDEC; s++) {
        const float* yin = (s & 1) ? yB : yA;
        float* yout      = (s & 1) ? yA : yB;
        const float* h0i = (s & 1) ? h0B : h0A;
        float* h0o       = (s & 1) ? h0A : h0B;
        const float* h1i = (s & 1) ? h1B : h1A;
        float* h1o       = (s & 1) ? h1A : h1B;

        phase_gru(yin, OO, h0i, h0o, Wih0, bih0, Whh0, bhh0, sm, tid, row, cg);
        gbar();
        phase_gru(h0o, MM, h1i, h1o, Wih1, bih1, Whh1, bhh1, sm, tid, row, cg);
        gbar();
        phase_fc1(h1o, fc1w, fc1b, sm, tid, row, cg);
        gbar();
        if (blockIdx.x < BB) phase_ln(lng, lnb, tid);
        gbar();
        if (blockIdx.x < BB) phase_fc2(fc2w, fc2b, out, s, sm, tid, row, cg);
        gbar();
        if (blockIdx.x < BB) phase_softmax(yout, tid);
        gbar();
    }
}

// ---------------- init / transpose / big GEMM ------------
__global__ void zero_init_kernel() {
    int i = blockIdx.x * blockDim.x + threadIdx.x;
    int stride = gridDim.x * blockDim.x;
    for (; i < BB * MM; i += stride) { g_e0A[i] = 0.f; g_e1A[i] = 0.f; }
}
__global__ void copy_y_kernel(const float* __restrict__ Y0) {
    int i = blockIdx.x * blockDim.x + threadIdx.x;
    if (i < BB * OO) g_yA[i] = Y0[i];
}
__global__ void transpose_x_kernel(const float* __restrict__ X) {
    int i = blockIdx.x * blockDim.x + threadIdx.x;
    int stride = gridDim.x * blockDim.x;
    const int total = TIN * BB * NIN;
    for (; i < total; i += stride) {
        int n = i % NIN;
        int r = i / NIN;
        int t = r / BB, b = r % BB;
        g_xt[i] = X[(b * TIN + t) * NIN + n];
    }
}

__global__ void __launch_bounds__(256) gemm_big_kernel(
    const float* __restrict__ A, const float* __restrict__ W,
    const float* __restrict__ bias, float* __restrict__ C,
    int K, int Cn)
{
    __shared__ __align__(16) float As[16][132];
    __shared__ __align__(16) float Bs[16][132];
    int tid = threadIdx.x;
    int tx = tid & 15, ty = tid >> 4;
    int r0 = blockIdx.y * 128, c0 = blockIdx.x * 128;
    ull acc[8][4];
#pragma unroll
    for (int i = 0; i < 8; i++)
#pragma unroll
        for (int j = 0; j < 4; j++) acc[i][j] = 0ull;
    for (int k0 = 0; k0 < K; k0 += 16) {
#pragma unroll
        for (int i = 0; i < 2; i++) {
            int q = tid + i * 256;
            int rr = q >> 2, kq = q & 3;
            float4 v = *(const float4*)(A + (size_t)(r0 + rr) * K + k0 + kq * 4);
            As[kq * 4 + 0][rr] = v.x; As[kq * 4 + 1][rr] = v.y;
            As[kq * 4 + 2][rr] = v.z; As[kq * 4 + 3][rr] = v.w;
        }
#pragma unroll
        for (int i = 0; i < 2; i++) {
            int q = tid + i * 256;
            int wn = q >> 2, kq = q & 3;
            float4 v = *(const float4*)(W + (size_t)(c0 + wn) * K + k0 + kq * 4);
            Bs[kq * 4 + 0][wn] = v.x; Bs[kq * 4 + 1][wn] = v.y;
            Bs[kq * 4 + 2][wn] = v.z; Bs[kq * 4 + 3][wn] = v.w;
        }
        __syncthreads();
#pragma unroll
        for (int kk = 0; kk < 16; kk++) {
            ulonglong2 bq0 = *(ulonglong2*)&Bs[kk][tx * 8];
            ulonglong2 bq1 = *(ulonglong2*)&Bs[kk][tx * 8 + 4];
            ull bp[4] = {bq0.x, bq0.y, bq1.x, bq1.y};
            float4 a0 = *(float4*)&As[kk][ty * 8];
            float4 a1 = *(float4*)&As[kk][ty * 8 + 4];
            float av[8] = {a0.x, a0.y, a0.z, a0.w, a1.x, a1.y, a1.z, a1.w};
#pragma unroll
            for (int i = 0; i < 8; i++) {
                ull ap;
                asm("mov.b64 %0, {%1,%1};" : "=l"(ap) : "f"(av[i]));
#pragma unroll
                for (int j = 0; j < 4; j++) fma2(acc[i][j], ap, bp[j]);
            }
        }
        __syncthreads();
    }
    int c = c0 + tx * 8;
    float4 bv0 = *(const float4*)(bias + c);
    float4 bv1 = *(const float4*)(bias + c + 4);
#pragma unroll
    for (int i = 0; i < 8; i++) {
        int r = r0 + ty * 8 + i;
        float2 p0, p1, p2, p3;
        asm("mov.b64 {%0,%1}, %2;" : "=f"(p0.x), "=f"(p0.y) : "l"(acc[i][0]));
        asm("mov.b64 {%0,%1}, %2;" : "=f"(p1.x), "=f"(p1.y) : "l"(acc[i][1]));
        asm("mov.b64 {%0,%1}, %2;" : "=f"(p2.x), "=f"(p2.y) : "l"(acc[i][2]));
        asm("mov.b64 {%0,%1}, %2;" : "=f"(p3.x), "=f"(p3.y) : "l"(acc[i][3]));
        float4 o0 = {p0.x + bv0.x, p0.y + bv0.y, p1.x + bv0.z, p1.y + bv0.w};
        float4 o1 = {p2.x + bv1.x, p2.y + bv1.y, p3.x + bv1.z, p3.y + bv1.w};
        *(float4*)(C + (size_t)r * Cn + c) = o0;
        *(float4*)(C + (size_t)r * Cn + c + 4) = o1;
    }
}

// ---------------- host launch ----------------
#define ENC_SM ((24 * 1024 + 2 * 8192) * 4)     // 163840 B
#define DEC_SM ((2 * 3072 + 2 * 8192) * 4)      // 90112 B

extern "C" void kernel_launch(void* const* d_in, const int* in_sizes, int n_in,
                              void* d_out, int out_size)
{
    const float* X        = (const float*)d_in[0];
    const float* Y0       = (const float*)d_in[1];
    const float* enc_Wih0 = (const float*)d_in[2];
    const float* enc_Whh0 = (const float*)d_in[3];
    const float* enc_bih0 = (const float*)d_in[4];
    const float* enc_bhh0 = (const float*)d_in[5];
    const float* enc_Wih1 = (const float*)d_in[6];
    const float* enc_Whh1 = (const float*)d_in[7];
    const float* enc_bih1 = (const float*)d_in[8];
    const float* enc_bhh1 = (const float*)d_in[9];
    const float* dec_Wih0 = (const float*)d_in[10];
    const float* dec_Whh0 = (const float*)d_in[11];
    const float* dec_bih0 = (const float*)d_in[12];
    const float* dec_bhh0 = (const float*)d_in[13];
    const float* dec_Wih1 = (const float*)d_in[14];
    const float* dec_Whh1 = (const float*)d_in[15];
    const float* dec_bih1 = (const float*)d_in[16];
    const float* dec_bhh1 = (const float*)d_in[17];
    const float* fc1_w    = (const float*)d_in[18];
    const float* fc1_b    = (const float*)d_in[19];
    const float* ln_g     = (const float*)d_in[20];
    const float* ln_b     = (const float*)d_in[21];
    const float* fc2_w    = (const float*)d_in[22];
    const float* fc2_b    = (const float*)d_in[23];
    float* out = (float*)d_out;

    float *xt, *gi, *seq0, *e0A, *e0B, *e1A, *e1B, *yA, *yB;
    cudaGetSymbolAddress((void**)&xt,   g_xt);
    cudaGetSymbolAddress((void**)&gi,   g_gi);
    cudaGetSymbolAddress((void**)&seq0, g_seq0);
    cudaGetSymbolAddress((void**)&e0A,  g_e0A);
    cudaGetSymbolAddress((void**)&e0B,  g_e0B);
    cudaGetSymbolAddress((void**)&e1A,  g_e1A);
    cudaGetSymbolAddress((void**)&e1B,  g_e1B);
    cudaGetSymbolAddress((void**)&yA,   g_yA);
    cudaGetSymbolAddress((void**)&yB,   g_yB);

    cudaFuncSetAttribute(enc_persist, cudaFuncAttributeMaxDynamicSharedMemorySize, ENC_SM);
    cudaFuncSetAttribute(dec_persist, cudaFuncAttributeMaxDynamicSharedMemorySize, DEC_SM);

    zero_init_kernel<<<256, 256>>>();
    copy_y_kernel<<<(BB * OO + 255) / 256, 256>>>(Y0);
    transpose_x_kernel<<<2048, 256>>>(X);

    const int R = TIN * BB;

    // encoder layer 0
    gemm_big_kernel<<<dim3(G3 / 128, R / 128), 256>>>(xt, enc_Wih0, enc_bih0, gi, NIN, G3);
    {
        const float* w = enc_Whh0; const float* b = enc_bhh0; const float* gp = gi;
        float* hA = e0A; float* hB = e0B; float* sq = seq0;
        void* args[] = {&w, &b, &gp, &hA, &hB, &sq};
        cudaLaunchCooperativeKernel((void*)enc_persist, dim3(128), dim3(256), args, (size_t)ENC_SM, (cudaStream_t)0);
    }

    // encoder layer 1
    gemm_big_kernel<<<dim3(G3 / 128, R / 128), 256>>>(seq0, enc_Wih1, enc_bih1, gi, MM, G3);
    {
        const float* w = enc_Whh1; const float* b = enc_bhh1; const float* gp = gi;
        float* hA = e1A; float* hB = e1B; float* sq = nullptr;
        void* args[] = {&w, &b, &gp, &hA, &hB, &sq};
        cudaLaunchCooperativeKernel((void*)enc_persist, dim3(128), dim3(256), args, (size_t)ENC_SM, (cudaStream_t)0);
    }

    // decoder: one persistent kernel, all 64 steps
    {
        float* outp = out;
        void* args[] = {&outp, &yA, &yB, &e0A, &e0B, &e1A, &e1B,
                        (void*)&dec_Wih0, (void*)&dec_bih0, (void*)&dec_Whh0, (void*)&dec_bhh0,
                        (void*)&dec_Wih1, (void*)&dec_bih1, (void*)&dec_Whh1, (void*)&dec_bhh1,
                        (void*)&fc1_w, (void*)&fc1_b, (void*)&ln_g, (void*)&ln_b,
                        (void*)&fc2_w, (void*)&fc2_b};
        cudaLaunchCooperativeKernel((void*)dec_persist, dim3(128), dim3(256), args, (size_t)DEC_SM, (cudaStream_t)0);
    }
}

// round 12
// speedup vs baseline: 2.4669x; 1.2594x over previous
#include <cuda_runtime.h>
#include <math.h>

#define BB   64
#define TIN  128
#define NIN  256
#define MM   1024
#define OO   512
#define LMM  2048
#define TDEC 64
#define G3   3072
typedef unsigned long long ull;

// ---------------- scratch ----------------
__device__ float g_xt[TIN * BB * NIN];
__device__ float g_gi[TIN * BB * G3];
__device__ float g_seq0[TIN * BB * MM];
__device__ float g_e0A[BB * MM], g_e0B[BB * MM];
__device__ float g_e1A[BB * MM], g_e1B[BB * MM];
__device__ float g_hT0A[BB * MM], g_hT0B[BB * MM];   // tf32-rounded h copies
__device__ float g_hT1A[BB * MM], g_hT1B[BB * MM];
__device__ float g_yA[BB * OO], g_yB[BB * OO];
__device__ float g_zpre[BB * LMM];
__device__ float g_z[BB * LMM];
__device__ float g_logits[BB * OO];
__device__ unsigned g_barc, g_barg;

// ---------------- helpers ----------------
__device__ __forceinline__ void fma2(ull& d, ull a, ull b) {
    asm("fma.rn.f32x2 %0, %1, %2, %0;" : "+l"(d) : "l"(a), "l"(b));
}
__device__ __forceinline__ float rsum(ull v) {
    float2 f;
    asm("mov.b64 {%0,%1}, %2;" : "=f"(f.x), "=f"(f.y) : "l"(v));
    return f.x + f.y;
}
__device__ __forceinline__ float sigf(float x) { return 1.f / (1.f + expf(-x)); }
__device__ __forceinline__ unsigned cvtTF(float x) {
    unsigned u; asm("cvt.rna.tf32.f32 %0, %1;" : "=r"(u) : "f"(x)); return u;
}
__device__ __forceinline__ void mma8(float* c, unsigned a0, unsigned a1, unsigned a2, unsigned a3,
                                     unsigned b0, unsigned b1) {
    asm("mma.sync.aligned.m16n8k8.row.col.f32.tf32.tf32.f32 "
        "{%0,%1,%2,%3},{%4,%5,%6,%7},{%8,%9},{%0,%1,%2,%3};"
        : "+f"(c[0]), "+f"(c[1]), "+f"(c[2]), "+f"(c[3])
        : "r"(a0), "r"(a1), "r"(a2), "r"(a3), "r"(b0), "r"(b1));
}

// device-wide barrier; co-residency guaranteed by cooperative launch
__device__ __forceinline__ void gbar() {
    __syncthreads();
    __threadfence();
    if (threadIdx.x == 0) {
        unsigned gen = ((volatile unsigned*)&g_barg)[0];
        if (atomicAdd(&g_barc, 1u) == gridDim.x - 1) {
            g_barc = 0;
            __threadfence();
            atomicAdd(&g_barg, 1u);
        } else {
            while (((volatile unsigned*)&g_barg)[0] == gen) {}
        }
    }
    __syncthreads();
}

// ================= encoder: persistent tf32-MMA layer =======================
// cooperative 128 blocks x 256 threads. Block owns 8 h-cols (24 gate rows of Whh,
// smem-resident tf32). 8 warps = 4 M-tiles x 2 interleaved K-halves.
#define WS_LD 1028
#define HT_LD 68
#define ENC2_SM ((24 * WS_LD + 2 * 64 * HT_LD) * 4)

__global__ void __launch_bounds__(256) enc_mma(
    const float* __restrict__ Whh, const float* __restrict__ bhh,
    const float* __restrict__ giB,
    float* hA, float* hB, float* hTA, float* hTB,
    float* seq)
{
    extern __shared__ float sm[];
    float* ws  = sm;                      // 24 x 1028 (tf32 bits as float)
    float* ht0 = sm + 24 * WS_LD;         // 64 x 68
    float* ht1 = ht0 + 64 * HT_LD;
    int tid = threadIdx.x;
    int lane = tid & 31, warp = tid >> 5;
    int g = lane >> 2, t4 = lane & 3;
    int mi = warp & 3, kh = warp >> 2;
    int cBase = blockIdx.x * 8;

    // stage weight slice once, rna-rounded to tf32
    for (int i = tid; i < 24 * 256; i += 256) {
        int r = i >> 8, kq = i & 255;
        int gRow = (r >> 3) * MM + cBase + (r & 7);
        float4 v = __ldg((const float4*)(Whh + (size_t)gRow * MM + kq * 4));
        uint4 u;
        u.x = cvtTF(v.x); u.y = cvtTF(v.y); u.z = cvtTF(v.z); u.w = cvtTF(v.w);
        *(uint4*)&ws[r * WS_LD + kq * 4] = u;
    }
    // per-thread epilogue biases (cols c0, c0+1)
    int c0 = cBase + 2 * t4;
    float br0 = bhh[c0],          br1 = bhh[c0 + 1];
    float bz0 = bhh[MM + c0],     bz1 = bhh[MM + c0 + 1];
    float bn0 = bhh[2 * MM + c0], bn1 = bhh[2 * MM + c0 + 1];
    __syncthreads();

    for (int t = 0; t < TIN; t++) {
        const float* hin  = (t & 1) ? hB : hA;
        float* hout       = (t & 1) ? hA : hB;
        const float* hinT = (t & 1) ? hTB : hTA;
        float* houtT      = (t & 1) ? hTA : hTB;

        float acc[3][4];
#pragma unroll
        for (int n = 0; n < 3; n++)
#pragma unroll
            for (int i = 0; i < 4; i++) acc[n][i] = 0.f;

        // stage chunk 0 (64 rows x 64 k)
#pragma unroll
        for (int i = 0; i < 4; i++) {
            int q = tid + i * 256;
            int row = q >> 4, kq = q & 15;
            float4 v = __ldcg((const float4*)(hinT + (size_t)row * MM + kq * 4));
            *(float4*)&ht0[row * HT_LD + kq * 4] = v;
        }
        __syncthreads();

#pragma unroll 1
        for (int ch = 0; ch < 16; ch++) {
            float* cur = (ch & 1) ? ht1 : ht0;
            float* nxt = (ch & 1) ? ht0 : ht1;
            float4 pf[4];
            if (ch < 15) {
#pragma unroll
                for (int i = 0; i < 4; i++) {
                    int q = tid + i * 256;
                    int row = q >> 4, kq = q & 15;
                    pf[i] = __ldcg((const float4*)(hinT + (size_t)row * MM + (ch + 1) * 64 + kq * 4));
                }
            }
            const unsigned* curu = (const unsigned*)cur;
            const unsigned* wsu  = (const unsigned*)ws;
            int arow0 = (16 * mi + g) * HT_LD;
            int arow1 = arow0 + 8 * HT_LD;
#pragma unroll
            for (int j = 0; j < 4; j++) {
                int k0 = (2 * j + kh) * 8;
                unsigned a0 = curu[arow0 + k0 + t4];
                unsigned a1 = curu[arow1 + k0 + t4];
                unsigned a2 = curu[arow0 + k0 + t4 + 4];
                unsigned a3 = curu[arow1 + k0 + t4 + 4];
                int kg = ch * 64 + k0 + t4;
#pragma unroll
                for (int nt = 0; nt < 3; nt++) {
                    unsigned b0 = wsu[(nt * 8 + g) * WS_LD + kg];
                    unsigned b1 = wsu[(nt * 8 + g) * WS_LD + kg + 4];
                    mma8(acc[nt], a0, a1, a2, a3, b0, b1);
                }
            }
            if (ch < 15) {
#pragma unroll
                for (int i = 0; i < 4; i++) {
                    int q = tid + i * 256;
                    int row = q >> 4, kq = q & 15;
                    *(float4*)&nxt[row * HT_LD + kq * 4] = pf[i];
                }
            }
            __syncthreads();
        }

        // reduce K-halves: warps 4-7 store, warps 0-3 add + epilogue
        float* red = ht1;
        if (kh == 1) {
#pragma unroll
            for (int n = 0; n < 3; n++)
#pragma unroll
                for (int i = 0; i < 4; i++)
                    red[(mi * 32 + lane) * 12 + n * 4 + i] = acc[n][i];
        }
        __syncthreads();
        if (kh == 0) {
#pragma unroll
            for (int n = 0; n < 3; n++)
#pragma unroll
                for (int i = 0; i < 4; i++)
                    acc[n][i] += red[(mi * 32 + lane) * 12 + n * 4 + i];

            int rbase = 16 * mi + g;
#pragma unroll
            for (int half = 0; half < 2; half++) {
                int row = rbase + half * 8;
                float gr0 = acc[0][2 * half], gr1 = acc[0][2 * half + 1];
                float gz0 = acc[1][2 * half], gz1 = acc[1][2 * half + 1];
                float gn0 = acc[2][2 * half], gn1 = acc[2][2 * half + 1];
                const float* gi = giB + ((size_t)t * BB + row) * G3;
                float2 gir = *(const float2*)(gi + c0);
                float2 giz = *(const float2*)(gi + MM + c0);
                float2 gin = *(const float2*)(gi + 2 * MM + c0);
                float2 hp = __ldcg((const float2*)(hin + (size_t)row * MM + c0));
                float R0 = sigf(gir.x + gr0 + br0);
                float R1 = sigf(gir.y + gr1 + br1);
                float Z0 = sigf(giz.x + gz0 + bz0);
                float Z1 = sigf(giz.y + gz1 + bz1);
                float N0 = tanhf(gin.x + R0 * (gn0 + bn0));
                float N1 = tanhf(gin.y + R1 * (gn1 + bn1));
                float2 ho = {(1.f - Z0) * N0 + Z0 * hp.x, (1.f - Z1) * N1 + Z1 * hp.y};
                *(float2*)(hout + (size_t)row * MM + c0) = ho;
                float2 hoT = {__uint_as_float(cvtTF(ho.x)), __uint_as_float(cvtTF(ho.y))};
                *(float2*)(houtT + (size_t)row * MM + c0) = hoT;
                if (seq) *(float2*)(seq + ((size_t)t * BB + row) * MM + c0) = ho;
            }
        }
        gbar();
    }
}

// ================= decoder (unchanged from R11, passing) ====================
template<bool CG>
__device__ __forceinline__ void loadH(float4 r[8], const float* src, int stride, int k0, int tid) {
#pragma unroll
    for (int i = 0; i < 8; i++) {
        int q = tid + i * 256;
        int row = q >> 5, kq = q & 31;
        const float4* p = (const float4*)(src + (size_t)row * stride + k0 + kq * 4);
        r[i] = CG ? __ldcg(p) : __ldg(p);
    }
}
__device__ __forceinline__ void stsH(float2* hs, const float4 r[8], int tid) {
#pragma unroll
    for (int i = 0; i < 8; i++) {
        int q = tid + i * 256;
        int row = q >> 5, kq = q & 31;
        int sw = row ^ kq;
        hs[(2 * kq) * 64 + sw]     = make_float2(r[i].x, r[i].y);
        hs[(2 * kq + 1) * 64 + sw] = make_float2(r[i].z, r[i].w);
    }
}
template<int NI>
__device__ __forceinline__ void loadWg(float4 r[NI], const float* W, int K, int cBase, int k0, int tid) {
#pragma unroll
    for (int i = 0; i < NI; i++) {
        int q = tid + i * 256;
        int e = q >> 5, kq = q & 31;
        int gRow = (e >> 3) * MM + cBase + (e & 7);
        r[i] = __ldg((const float4*)(W + (size_t)gRow * K + k0 + kq * 4));
    }
}
template<int NI>
__device__ __forceinline__ void loadWf(float4 r[NI], const float* W, int K, int cBase, int k0, int tid) {
#pragma unroll
    for (int i = 0; i < NI; i++) {
        int q = tid + i * 256;
        int e = q >> 5, kq = q & 31;
        r[i] = __ldg((const float4*)(W + (size_t)(cBase + e) * K + k0 + kq * 4));
    }
}
template<int NI>
__device__ __forceinline__ void stsW(float* wc, const float4 r[NI], int tid) {
#pragma unroll
    for (int i = 0; i < NI; i++) {
        int q = tid + i * 256;
        int e = q >> 5, kq = q & 31;
        *(float4*)&wc[e * 128 + kq * 4] = r[i];
    }
}
__device__ __forceinline__ void gruAccS(const float2* hs, const float* w, int wstride, int kOff,
                                        int row, int cg, ull acc[6]) {
#pragma unroll 8
    for (int i = 0; i < 32; i++) {
        int sw = row ^ i;
        ull h0 = *(const ull*)&hs[(2 * i) * 64 + sw];
        ull h1 = *(const ull*)&hs[(2 * i + 1) * 64 + sw];
#pragma unroll
        for (int g = 0; g < 3; g++)
#pragma unroll
            for (int j = 0; j < 2; j++) {
                ulonglong2 wv = *(const ulonglong2*)&w[(size_t)(g * 8 + cg * 2 + j) * wstride + kOff + i * 4];
                fma2(acc[g * 2 + j], h0, wv.x);
                fma2(acc[g * 2 + j], h1, wv.y);
            }
    }
}
template<int NO>
__device__ __forceinline__ void fcAcc(const float2* hs, const float* wc, int row, int cg, ull* acc) {
#pragma unroll 8
    for (int i = 0; i < 32; i++) {
        int sw = row ^ i;
        ull h0 = *(const ull*)&hs[(2 * i) * 64 + sw];
        ull h1 = *(const ull*)&hs[(2 * i + 1) * 64 + sw];
#pragma unroll
        for (int j = 0; j < NO; j++) {
            ulonglong2 wv = *(const ulonglong2*)&wc[(cg * NO + j) * 128 + i * 4];
            fma2(acc[j], h0, wv.x);
            fma2(acc[j], h1, wv.y);
        }
    }
}

__device__ __forceinline__ void phase_gru(
    const float* x, int Kx, const float* hin, float* hout,
    const float* Wih, const float* bih, const float* Whh, const float* bhh,
    float* sm, int tid, int row, int cg)
{
    float* wcA = sm; float* wcB = sm + 3072;
    float2* hsA = (float2*)(sm + 6144); float2* hsB = hsA + 4096;
    int cBase = blockIdx.x * 8;
    int xc = Kx / 128, NC = xc + 8;

    ull accA[6], accB[6];
#pragma unroll
    for (int a = 0; a < 6; a++) { accA[a] = 0ull; accB[a] = 0ull; }

    float4 sh[8]; float4 swr[3];
    loadH<true>(sh, x, Kx, 0, tid);
    loadWg<3>(swr, Wih, Kx, cBase, 0, tid);
    stsH(hsA, sh, tid); stsW<3>(wcA, swr, tid);
    __syncthreads();
    float2* curH = hsA; float2* nxtH = hsB;
    float* curW = wcA; float* nxtW = wcB;
#pragma unroll 1
    for (int ch = 0; ch < NC; ch++) {
        if (ch + 1 < NC) {
            int nc = ch + 1;
            if (nc < xc) {
                loadH<true>(sh, x, Kx, nc * 128, tid);
                loadWg<3>(swr, Wih, Kx, cBase, nc * 128, tid);
            } else {
                loadH<true>(sh, hin, MM, (nc - xc) * 128, tid);
                loadWg<3>(swr, Whh, MM, cBase, (nc - xc) * 128, tid);
            }
        }
        if (ch < xc) gruAccS(curH, curW, 128, 0, row, cg, accA);
        else         gruAccS(curH, curW, 128, 0, row, cg, accB);
        if (ch + 1 < NC) { stsH(nxtH, sh, tid); stsW<3>(nxtW, swr, tid); }
        __syncthreads();
        float2* t1 = curH; curH = nxtH; nxtH = t1;
        float* t2 = curW; curW = nxtW; nxtW = t2;
    }

    int c = cBase + cg * 2;
    float2 bri = *(const float2*)(bih + c);
    float2 bzi = *(const float2*)(bih + MM + c);
    float2 bni = *(const float2*)(bih + 2 * MM + c);
    float2 brh = *(const float2*)(bhh + c);
    float2 bzh = *(const float2*)(bhh + MM + c);
    float2 bnh = *(const float2*)(bhh + 2 * MM + c);
    float2 hp = __ldcg((const float2*)(hin + (size_t)row * MM + c));
    float r0 = sigf(rsum(accA[0]) + bri.x + rsum(accB[0]) + brh.x);
    float r1 = sigf(rsum(accA[1]) + bri.y + rsum(accB[1]) + brh.y);
    float z0 = sigf(rsum(accA[2]) + bzi.x + rsum(accB[2]) + bzh.x);
    float z1 = sigf(rsum(accA[3]) + bzi.y + rsum(accB[3]) + bzh.y);
    float n0 = tanhf(rsum(accA[4]) + bni.x + r0 * (rsum(accB[4]) + bnh.x));
    float n1 = tanhf(rsum(accA[5]) + bni.y + r1 * (rsum(accB[5]) + bnh.y));
    float2 ho = {(1.f - z0) * n0 + z0 * hp.x, (1.f - z1) * n1 + z1 * hp.y};
    *(float2*)(hout + (size_t)row * MM + c) = ho;
}

__device__ __forceinline__ void phase_fc1(
    const float* A, const float* W, const float* bias,
    float* sm, int tid, int row, int cg)
{
    float* wcA = sm; float* wcB = sm + 2048;
    float2* hsA = (float2*)(sm + 4096); float2* hsB = hsA + 4096;
    int cBase = blockIdx.x * 16;
    ull acc[4] = {0ull, 0ull, 0ull, 0ull};

    float4 sh[8]; float4 swr[2];
    loadH<true>(sh, A, MM, 0, tid);
    loadWf<2>(swr, W, MM, cBase, 0, tid);
    stsH(hsA, sh, tid); stsW<2>(wcA, swr, tid);
    __syncthreads();
    float2* curH = hsA; float2* nxtH = hsB;
    float* curW = wcA; float* nxtW = wcB;
#pragma unroll 1
    for (int ch = 0; ch < 8; ch++) {
        if (ch < 7) {
            loadH<true>(sh, A, MM, (ch + 1) * 128, tid);
            loadWf<2>(swr, W, MM, cBase, (ch + 1) * 128, tid);
        }
        fcAcc<4>(curH, curW, row, cg, acc);
        if (ch < 7) { stsH(nxtH, sh, tid); stsW<2>(nxtW, swr, tid); }
        __syncthreads();
        float2* t1 = curH; curH = nxtH; nxtH = t1;
        float* t2 = curW; curW = nxtW; nxtW = t2;
    }
    int c = cBase + cg * 4;
    float4 bv = *(const float4*)(bias + c);
    float4 o = {rsum(acc[0]) + bv.x, rsum(acc[1]) + bv.y,
                rsum(acc[2]) + bv.z, rsum(acc[3]) + bv.w};
    *(float4*)(g_zpre + (size_t)row * LMM + c) = o;
}

__device__ __forceinline__ void phase_ln(const float* g, const float* bta, int tid)
{
    int b = blockIdx.x;
    float v[8];
    float s = 0.f, s2 = 0.f;
#pragma unroll
    for (int j = 0; j < 8; j++) {
        float t = __ldcg(&g_zpre[(size_t)b * LMM + tid + j * 256]);
        v[j] = t; s += t; s2 += t * t;
    }
    __shared__ float red[64];
#pragma unroll
    for (int o = 16; o; o >>= 1) {
        s += __shfl_down_sync(0xffffffffu, s, o);
        s2 += __shfl_down_sync(0xffffffffu, s2, o);
    }
    int w = tid >> 5, l = tid & 31;
    if (l == 0) { red[w] = s; red[32 + w] = s2; }
    __syncthreads();
    if (tid == 0) {
        float a = 0.f, a2 = 0.f;
        for (int i = 0; i < 8; i++) { a += red[i]; a2 += red[32 + i]; }
        red[0] = a; red[32] = a2;
    }
    __syncthreads();
    float mu = red[0] * (1.f / (float)LMM);
    float var = red[32] * (1.f / (float)LMM) - mu * mu;
    float rs = rsqrtf(var + 1e-5f);
#pragma unroll
    for (int j = 0; j < 8; j++) {
        int cc = tid + j * 256;
        float t = (v[j] - mu) * rs * g[cc] + bta[cc];
        g_z[(size_t)b * LMM + cc] = t * normcdff(t);
    }
}

__device__ __forceinline__ void phase_fc2(
    const float* W, const float* bias, float* out, int s,
    float* sm, int tid, int row, int cg)
{
    float* wcA = sm; float* wcB = sm + 1024;
    float2* hsA = (float2*)(sm + 2048); float2* hsB = hsA + 4096;
    int cBase = blockIdx.x * 8;
    ull acc[2] = {0ull, 0ull};

    float4 sh[8]; float4 swr[1];
    loadH<true>(sh, g_z, LMM, 0, tid);
    loadWf<1>(swr, W, LMM, cBase, 0, tid);
    stsH(hsA, sh, tid); stsW<1>(wcA, swr, tid);
    __syncthreads();
    float2* curH = hsA; float2* nxtH = hsB;
    float* curW = wcA; float* nxtW = wcB;
#pragma unroll 1
    for (int ch = 0; ch < 16; ch++) {
        if (ch < 15) {
            loadH<true>(sh, g_z, LMM, (ch + 1) * 128, tid);
            loadWf<1>(swr, W, LMM, cBase, (ch + 1) * 128, tid);
        }
        fcAcc<2>(curH, curW, row, cg, acc);
        if (ch < 15) { stsH(nxtH, sh, tid); stsW<1>(nxtW, swr, tid); }
        __syncthreads();
        float2* t1 = curH; curH = nxtH; nxtH = t1;
        float* t2 = curW; curW = nxtW; nxtW = t2;
    }
    int c = cBase + cg * 2;
    float2 bv = *(const float2*)(bias + c);
    float2 o = {rsum(acc[0]) + bv.x, rsum(acc[1]) + bv.y};
    *(float2*)(g_logits + (size_t)row * OO + c) = o;
    *(float2*)(out + ((size_t)row * TDEC + s) * OO + c) = o;
}

__device__ __forceinline__ void phase_softmax(float* yout, int tid)
{
    int b = blockIdx.x;
    float v0 = __ldcg(&g_logits[(size_t)b * OO + tid]);
    float v1 = __ldcg(&g_logits[(size_t)b * OO + 256 + tid]);
    __shared__ float sred[9];
    int w = tid >> 5, l = tid & 31;
    float m = fmaxf(v0, v1);
#pragma unroll
    for (int d = 16; d; d >>= 1) m = fmaxf(m, __shfl_down_sync(0xffffffffu, m, d));
    if (l == 0) sred[w] = m;
    __syncthreads();
    if (tid == 0) {
        float a = sred[0];
        for (int i = 1; i < 8; i++) a = fmaxf(a, sred[i]);
        sred[8] = a;
    }
    __syncthreads();
    float mx = sred[8];
    float e0 = expf(v0 - mx), e1 = expf(v1 - mx);
    float su = e0 + e1;
#pragma unroll
    for (int d = 16; d; d >>= 1) su += __shfl_down_sync(0xffffffffu, su, d);
    __syncthreads();
    if (l == 0) sred[w] = su;
    __syncthreads();
    if (tid == 0) {
        float a = 0.f;
        for (int i = 0; i < 8; i++) a += sred[i];
        sred[8] = a;
    }
    __syncthreads();
    float inv = 1.f / sred[8];
    yout[(size_t)b * OO + tid]       = e0 * inv;
    yout[(size_t)b * OO + 256 + tid] = e1 * inv;
}

__global__ void __launch_bounds__(256) dec_persist(
    float* __restrict__ out,
    float* yA, float* yB, float* h0A, float* h0B, float* h1A, float* h1B,
    const float* __restrict__ Wih0, const float* __restrict__ bih0,
    const float* __restrict__ Whh0, const float* __restrict__ bhh0,
    const float* __restrict__ Wih1, const float* __restrict__ bih1,
    const float* __restrict__ Whh1, const float* __restrict__ bhh1,
    const float* __restrict__ fc1w, const float* __restrict__ fc1b,
    const float* __restrict__ lng, const float* __restrict__ lnb,
    const float* __restrict__ fc2w, const float* __restrict__ fc2b)
{
    extern __shared__ float sm[];
    int tid = threadIdx.x, row = tid & 63, cg = tid >> 6;

    for (int s = 0; s < TDEC; s++) {
        const float* yin = (s & 1) ? yB : yA;
        float* yout      = (s & 1) ? yA : yB;
        const float* h0i = (s & 1) ? h0B : h0A;
        float* h0o       = (s & 1) ? h0A : h0B;
        const float* h1i = (s & 1) ? h1B : h1A;
        float* h1o       = (s & 1) ? h1A : h1B;

        phase_gru(yin, OO, h0i, h0o, Wih0, bih0, Whh0, bhh0, sm, tid, row, cg);
        gbar();
        phase_gru(h0o, MM, h1i, h1o, Wih1, bih1, Whh1, bhh1, sm, tid, row, cg);
        gbar();
        phase_fc1(h1o, fc1w, fc1b, sm, tid, row, cg);
        gbar();
        if (blockIdx.x < BB) phase_ln(lng, lnb, tid);
        gbar();
        if (blockIdx.x < BB) phase_fc2(fc2w, fc2b, out, s, sm, tid, row, cg);
        gbar();
        if (blockIdx.x < BB) phase_softmax(yout, tid);
        gbar();
    }
}

// ---------------- init / transpose / big GEMM ------------
__global__ void zero_init_kernel() {
    int i = blockIdx.x * blockDim.x + threadIdx.x;
    int stride = gridDim.x * blockDim.x;
    for (; i < BB * MM; i += stride) {
        g_e0A[i] = 0.f; g_e1A[i] = 0.f;
        g_hT0A[i] = 0.f; g_hT1A[i] = 0.f;
    }
}
__global__ void copy_y_kernel(const float* __restrict__ Y0) {
    int i = blockIdx.x * blockDim.x + threadIdx.x;
    if (i < BB * OO) g_yA[i] = Y0[i];
}
__global__ void transpose_x_kernel(const float* __restrict__ X) {
    int i = blockIdx.x * blockDim.x + threadIdx.x;
    int stride = gridDim.x * blockDim.x;
    const int total = TIN * BB * NIN;
    for (; i < total; i += stride) {
        int n = i % NIN;
        int r = i / NIN;
        int t = r / BB, b = r % BB;
        g_xt[i] = X[(b * TIN + t) * NIN + n];
    }
}

__global__ void __launch_bounds__(256) gemm_big_kernel(
    const float* __restrict__ A, const float* __restrict__ W,
    const float* __restrict__ bias, float* __restrict__ C,
    int K, int Cn)
{
    __shared__ __align__(16) float As[16][132];
    __shared__ __align__(16) float Bs[16][132];
    int tid = threadIdx.x;
    int tx = tid & 15, ty = tid >> 4;
    int r0 = blockIdx.y * 128, c0 = blockIdx.x * 128;
    ull acc[8][4];
#pragma unroll
    for (int i = 0; i < 8; i++)
#pragma unroll
        for (int j = 0; j < 4; j++) acc[i][j] = 0ull;
    for (int k0 = 0; k0 < K; k0 += 16) {
#pragma unroll
        for (int i = 0; i < 2; i++) {
            int q = tid + i * 256;
            int rr = q >> 2, kq = q & 3;
            float4 v = *(const float4*)(A + (size_t)(r0 + rr) * K + k0 + kq * 4);
            As[kq * 4 + 0][rr] = v.x; As[kq * 4 + 1][rr] = v.y;
            As[kq * 4 + 2][rr] = v.z; As[kq * 4 + 3][rr] = v.w;
        }
#pragma unroll
        for (int i = 0; i < 2; i++) {
            int q = tid + i * 256;
            int wn = q >> 2, kq = q & 3;
            float4 v = *(const float4*)(W + (size_t)(c0 + wn) * K + k0 + kq * 4);
            Bs[kq * 4 + 0][wn] = v.x; Bs[kq * 4 + 1][wn] = v.y;
            Bs[kq * 4 + 2][wn] = v.z; Bs[kq * 4 + 3][wn] = v.w;
        }
        __syncthreads();
#pragma unroll
        for (int kk = 0; kk < 16; kk++) {
            ulonglong2 bq0 = *(ulonglong2*)&Bs[kk][tx * 8];
            ulonglong2 bq1 = *(ulonglong2*)&Bs[kk][tx * 8 + 4];
            ull bp[4] = {bq0.x, bq0.y, bq1.x, bq1.y};
            float4 a0 = *(float4*)&As[kk][ty * 8];
            float4 a1 = *(float4*)&As[kk][ty * 8 + 4];
            float av[8] = {a0.x, a0.y, a0.z, a0.w, a1.x, a1.y, a1.z, a1.w};
#pragma unroll
            for (int i = 0; i < 8; i++) {
                ull ap;
                asm("mov.b64 %0, {%1,%1};" : "=l"(ap) : "f"(av[i]));
#pragma unroll
                for (int j = 0; j < 4; j++) fma2(acc[i][j], ap, bp[j]);
            }
        }
        __syncthreads();
    }
    int c = c0 + tx * 8;
    float4 bv0 = *(const float4*)(bias + c);
    float4 bv1 = *(const float4*)(bias + c + 4);
#pragma unroll
    for (int i = 0; i < 8; i++) {
        int r = r0 + ty * 8 + i;
        float2 p0, p1, p2, p3;
        asm("mov.b64 {%0,%1}, %2;" : "=f"(p0.x), "=f"(p0.y) : "l"(acc[i][0]));
        asm("mov.b64 {%0,%1}, %2;" : "=f"(p1.x), "=f"(p1.y) : "l"(acc[i][1]));
        asm("mov.b64 {%0,%1}, %2;" : "=f"(p2.x), "=f"(p2.y) : "l"(acc[i][2]));
        asm("mov.b64 {%0,%1}, %2;" : "=f"(p3.x), "=f"(p3.y) : "l"(acc[i][3]));
        float4 o0 = {p0.x + bv0.x, p0.y + bv0.y, p1.x + bv0.z, p1.y + bv0.w};
        float4 o1 = {p2.x + bv1.x, p2.y + bv1.y, p3.x + bv1.z, p3.y + bv1.w};
        *(float4*)(C + (size_t)r * Cn + c) = o0;
        *(float4*)(C + (size_t)r * Cn + c + 4) = o1;
    }
}

// ---------------- host launch ----------------
#define DEC_SM ((2 * 3072 + 2 * 8192) * 4)      // 90112 B

extern "C" void kernel_launch(void* const* d_in, const int* in_sizes, int n_in,
                              void* d_out, int out_size)
{
    const float* X        = (const float*)d_in[0];
    const float* Y0       = (const float*)d_in[1];
    const float* enc_Wih0 = (const float*)d_in[2];
    const float* enc_Whh0 = (const float*)d_in[3];
    const float* enc_bih0 = (const float*)d_in[4];
    const float* enc_bhh0 = (const float*)d_in[5];
    const float* enc_Wih1 = (const float*)d_in[6];
    const float* enc_Whh1 = (const float*)d_in[7];
    const float* enc_bih1 = (const float*)d_in[8];
    const float* enc_bhh1 = (const float*)d_in[9];
    const float* dec_Wih0 = (const float*)d_in[10];
    const float* dec_Whh0 = (const float*)d_in[11];
    const float* dec_bih0 = (const float*)d_in[12];
    const float* dec_bhh0 = (const float*)d_in[13];
    const float* dec_Wih1 = (const float*)d_in[14];
    const float* dec_Whh1 = (const float*)d_in[15];
    const float* dec_bih1 = (const float*)d_in[16];
    const float* dec_bhh1 = (const float*)d_in[17];
    const float* fc1_w    = (const float*)d_in[18];
    const float* fc1_b    = (const float*)d_in[19];
    const float* ln_g     = (const float*)d_in[20];
    const float* ln_b     = (const float*)d_in[21];
    const float* fc2_w    = (const float*)d_in[22];
    const float* fc2_b    = (const float*)d_in[23];
    float* out = (float*)d_out;

    float *xt, *gi, *seq0, *e0A, *e0B, *e1A, *e1B, *yA, *yB;
    float *hT0A, *hT0B, *hT1A, *hT1B;
    cudaGetSymbolAddress((void**)&xt,   g_xt);
    cudaGetSymbolAddress((void**)&gi,   g_gi);
    cudaGetSymbolAddress((void**)&seq0, g_seq0);
    cudaGetSymbolAddress((void**)&e0A,  g_e0A);
    cudaGetSymbolAddress((void**)&e0B,  g_e0B);
    cudaGetSymbolAddress((void**)&e1A,  g_e1A);
    cudaGetSymbolAddress((void**)&e1B,  g_e1B);
    cudaGetSymbolAddress((void**)&hT0A, g_hT0A);
    cudaGetSymbolAddress((void**)&hT0B, g_hT0B);
    cudaGetSymbolAddress((void**)&hT1A, g_hT1A);
    cudaGetSymbolAddress((void**)&hT1B, g_hT1B);
    cudaGetSymbolAddress((void**)&yA,   g_yA);
    cudaGetSymbolAddress((void**)&yB,   g_yB);

    cudaFuncSetAttribute(enc_mma,     cudaFuncAttributeMaxDynamicSharedMemorySize, ENC2_SM);
    cudaFuncSetAttribute(dec_persist, cudaFuncAttributeMaxDynamicSharedMemorySize, DEC_SM);

    zero_init_kernel<<<256, 256>>>();
    copy_y_kernel<<<(BB * OO + 255) / 256, 256>>>(Y0);
    transpose_x_kernel<<<2048, 256>>>(X);

    const int R = TIN * BB;

    // encoder layer 0
    gemm_big_kernel<<<dim3(G3 / 128, R / 128), 256>>>(xt, enc_Wih0, enc_bih0, gi, NIN, G3);
    {
        const float* w = enc_Whh0; const float* b = enc_bhh0; const float* gp = gi;
        float* hA = e0A; float* hB = e0B; float* hTA = hT0A; float* hTB = hT0B; float* sq = seq0;
        void* args[] = {&w, &b, &gp, &hA, &hB, &hTA, &hTB, &sq};
        cudaLaunchCooperativeKernel((void*)enc_mma, dim3(128), dim3(256), args, (size_t)ENC2_SM, (cudaStream_t)0);
    }

    // encoder layer 1
    gemm_big_kernel<<<dim3(G3 / 128, R / 128), 256>>>(seq0, enc_Wih1, enc_bih1, gi, MM, G3);
    {
        const float* w = enc_Whh1; const float* b = enc_bhh1; const float* gp = gi;
        float* hA = e1A; float* hB = e1B; float* hTA = hT1A; float* hTB = hT1B; float* sq = nullptr;
        void* args[] = {&w, &b, &gp, &hA, &hB, &hTA, &hTB, &sq};
        cudaLaunchCooperativeKernel((void*)enc_mma, dim3(128), dim3(256), args, (size_t)ENC2_SM, (cudaStream_t)0);
    }

    // decoder: one persistent kernel, all 64 steps
    {
        float* outp = out;
        void* args[] = {&outp, &yA, &yB, &e0A, &e0B, &e1A, &e1B,
                        (void*)&dec_Wih0, (void*)&dec_bih0, (void*)&dec_Whh0, (void*)&dec_bhh0,
                        (void*)&dec_Wih1, (void*)&dec_bih1, (void*)&dec_Whh1, (void*)&dec_bhh1,
                        (void*)&fc1_w, (void*)&fc1_b, (void*)&ln_g, (void*)&ln_b,
                        (void*)&fc2_w, (void*)&fc2_b};
        cudaLaunchCooperativeKernel((void*)dec_persist, dim3(128), dim3(256), args, (size_t)DEC_SM, (cudaStream_t)0);
    }
}

// round 14
// speedup vs baseline: 3.0316x; 1.2289x over previous
#include <cuda_runtime.h>
#include <math.h>

#define BB   64
#define TIN  128
#define NIN  256
#define MM   1024
#define OO   512
#define LMM  2048
#define TDEC 64
#define G3   3072
typedef unsigned long long ull;

// ---------------- scratch ----------------
__device__ float g_xt[TIN * BB * NIN];
__device__ float g_gi[TIN * BB * G3];
__device__ float g_seq0[TIN * BB * MM];
__device__ float g_e0A[BB * MM], g_e0B[BB * MM];
__device__ float g_e1A[BB * MM], g_e1B[BB * MM];
__device__ float g_hT0A[BB * MM], g_hT0B[BB * MM];
__device__ float g_hT1A[BB * MM], g_hT1B[BB * MM];
__device__ float g_yA[BB * OO], g_yB[BB * OO];
__device__ float g_zpre[BB * LMM];
__device__ float g_z[BB * LMM];
__device__ float g_logits[BB * OO];
__device__ unsigned g_barc, g_barg;
// tf32 pre-converted decoder GRU weights
__device__ float g_tWih0[G3 * OO];
__device__ float g_tWhh0[G3 * MM];
__device__ float g_tWih1[G3 * MM];
__device__ float g_tWhh1[G3 * MM];

// ---------------- helpers ----------------
__device__ __forceinline__ void fma2(ull& d, ull a, ull b) {
    asm("fma.rn.f32x2 %0, %1, %2, %0;" : "+l"(d) : "l"(a), "l"(b));
}
__device__ __forceinline__ float rsum(ull v) {
    float2 f;
    asm("mov.b64 {%0,%1}, %2;" : "=f"(f.x), "=f"(f.y) : "l"(v));
    return f.x + f.y;
}
__device__ __forceinline__ float sigf(float x) { return 1.f / (1.f + expf(-x)); }
__device__ __forceinline__ unsigned cvtTF(float x) {
    unsigned u; asm("cvt.rna.tf32.f32 %0, %1;" : "=r"(u) : "f"(x)); return u;
}
__device__ __forceinline__ void mma8(float* c, unsigned a0, unsigned a1, unsigned a2, unsigned a3,
                                     unsigned b0, unsigned b1) {
    asm("mma.sync.aligned.m16n8k8.row.col.f32.tf32.tf32.f32 "
        "{%0,%1,%2,%3},{%4,%5,%6,%7},{%8,%9},{%0,%1,%2,%3};"
        : "+f"(c[0]), "+f"(c[1]), "+f"(c[2]), "+f"(c[3])
        : "r"(a0), "r"(a1), "r"(a2), "r"(a3), "r"(b0), "r"(b1));
}

__device__ __forceinline__ void gbar() {
    __syncthreads();
    __threadfence();
    if (threadIdx.x == 0) {
        unsigned gen = ((volatile unsigned*)&g_barg)[0];
        if (atomicAdd(&g_barc, 1u) == gridDim.x - 1) {
            g_barc = 0;
            __threadfence();
            atomicAdd(&g_barg, 1u);
        } else {
            while (((volatile unsigned*)&g_barg)[0] == gen) {}
        }
    }
    __syncthreads();
}

// ================= encoder: persistent tf32-MMA layer (R12, passing) ========
#define WS_LD 1028
#define HT_LD 68
#define ENC2_SM ((24 * WS_LD + 2 * 64 * HT_LD) * 4)

__global__ void __launch_bounds__(256) enc_mma(
    const float* __restrict__ Whh, const float* __restrict__ bhh,
    const float* __restrict__ giB,
    float* hA, float* hB, float* hTA, float* hTB,
    float* seq)
{
    extern __shared__ float sm[];
    float* ws  = sm;
    float* ht0 = sm + 24 * WS_LD;
    float* ht1 = ht0 + 64 * HT_LD;
    int tid = threadIdx.x;
    int lane = tid & 31, warp = tid >> 5;
    int g = lane >> 2, t4 = lane & 3;
    int mi = warp & 3, kh = warp >> 2;
    int cBase = blockIdx.x * 8;

    for (int i = tid; i < 24 * 256; i += 256) {
        int r = i >> 8, kq = i & 255;
        int gRow = (r >> 3) * MM + cBase + (r & 7);
        float4 v = __ldg((const float4*)(Whh + (size_t)gRow * MM + kq * 4));
        uint4 u;
        u.x = cvtTF(v.x); u.y = cvtTF(v.y); u.z = cvtTF(v.z); u.w = cvtTF(v.w);
        *(uint4*)&ws[r * WS_LD + kq * 4] = u;
    }
    int c0 = cBase + 2 * t4;
    float br0 = bhh[c0],          br1 = bhh[c0 + 1];
    float bz0 = bhh[MM + c0],     bz1 = bhh[MM + c0 + 1];
    float bn0 = bhh[2 * MM + c0], bn1 = bhh[2 * MM + c0 + 1];
    __syncthreads();

    for (int t = 0; t < TIN; t++) {
        const float* hin  = (t & 1) ? hB : hA;
        float* hout       = (t & 1) ? hA : hB;
        const float* hinT = (t & 1) ? hTB : hTA;
        float* houtT      = (t & 1) ? hTA : hTB;

        float acc[3][4];
#pragma unroll
        for (int n = 0; n < 3; n++)
#pragma unroll
            for (int i = 0; i < 4; i++) acc[n][i] = 0.f;

#pragma unroll
        for (int i = 0; i < 4; i++) {
            int q = tid + i * 256;
            int row = q >> 4, kq = q & 15;
            float4 v = __ldcg((const float4*)(hinT + (size_t)row * MM + kq * 4));
            *(float4*)&ht0[row * HT_LD + kq * 4] = v;
        }
        __syncthreads();

#pragma unroll 1
        for (int ch = 0; ch < 16; ch++) {
            float* cur = (ch & 1) ? ht1 : ht0;
            float* nxt = (ch & 1) ? ht0 : ht1;
            float4 pf[4];
            if (ch < 15) {
#pragma unroll
                for (int i = 0; i < 4; i++) {
                    int q = tid + i * 256;
                    int row = q >> 4, kq = q & 15;
                    pf[i] = __ldcg((const float4*)(hinT + (size_t)row * MM + (ch + 1) * 64 + kq * 4));
                }
            }
            const unsigned* curu = (const unsigned*)cur;
            const unsigned* wsu  = (const unsigned*)ws;
            int arow0 = (16 * mi + g) * HT_LD;
            int arow1 = arow0 + 8 * HT_LD;
#pragma unroll
            for (int j = 0; j < 4; j++) {
                int k0 = (2 * j + kh) * 8;
                unsigned a0 = curu[arow0 + k0 + t4];
                unsigned a1 = curu[arow1 + k0 + t4];
                unsigned a2 = curu[arow0 + k0 + t4 + 4];
                unsigned a3 = curu[arow1 + k0 + t4 + 4];
                int kg = ch * 64 + k0 + t4;
#pragma unroll
                for (int nt = 0; nt < 3; nt++) {
                    unsigned b0 = wsu[(nt * 8 + g) * WS_LD + kg];
                    unsigned b1 = wsu[(nt * 8 + g) * WS_LD + kg + 4];
                    mma8(acc[nt], a0, a1, a2, a3, b0, b1);
                }
            }
            if (ch < 15) {
#pragma unroll
                for (int i = 0; i < 4; i++) {
                    int q = tid + i * 256;
                    int row = q >> 4, kq = q & 15;
                    *(float4*)&nxt[row * HT_LD + kq * 4] = pf[i];
                }
            }
            __syncthreads();
        }

        float* red = ht1;
        if (kh == 1) {
#pragma unroll
            for (int n = 0; n < 3; n++)
#pragma unroll
                for (int i = 0; i < 4; i++)
                    red[(mi * 32 + lane) * 12 + n * 4 + i] = acc[n][i];
        }
        __syncthreads();
        if (kh == 0) {
#pragma unroll
            for (int n = 0; n < 3; n++)
#pragma unroll
                for (int i = 0; i < 4; i++)
                    acc[n][i] += red[(mi * 32 + lane) * 12 + n * 4 + i];

            int rbase = 16 * mi + g;
#pragma unroll
            for (int half = 0; half < 2; half++) {
                int row = rbase + half * 8;
                float gr0 = acc[0][2 * half], gr1 = acc[0][2 * half + 1];
                float gz0 = acc[1][2 * half], gz1 = acc[1][2 * half + 1];
                float gn0 = acc[2][2 * half], gn1 = acc[2][2 * half + 1];
                const float* gi = giB + ((size_t)t * BB + row) * G3;
                float2 gir = *(const float2*)(gi + c0);
                float2 giz = *(const float2*)(gi + MM + c0);
                float2 gin = *(const float2*)(gi + 2 * MM + c0);
                float2 hp = __ldcg((const float2*)(hin + (size_t)row * MM + c0));
                float R0 = sigf(gir.x + gr0 + br0);
                float R1 = sigf(gir.y + gr1 + br1);
                float Z0 = sigf(giz.x + gz0 + bz0);
                float Z1 = sigf(giz.y + gz1 + bz1);
                float N0 = tanhf(gin.x + R0 * (gn0 + bn0));
                float N1 = tanhf(gin.y + R1 * (gn1 + bn1));
                float2 ho = {(1.f - Z0) * N0 + Z0 * hp.x, (1.f - Z1) * N1 + Z1 * hp.y};
                *(float2*)(hout + (size_t)row * MM + c0) = ho;
                float2 hoT = {__uint_as_float(cvtTF(ho.x)), __uint_as_float(cvtTF(ho.y))};
                *(float2*)(houtT + (size_t)row * MM + c0) = hoT;
                if (seq) *(float2*)(seq + ((size_t)t * BB + row) * MM + c0) = ho;
            }
        }
        gbar();
    }
}

// ================= decoder scalar helpers (fc1/fc2 still use these) =========
template<bool CG>
__device__ __forceinline__ void loadH(float4 r[8], const float* src, int stride, int k0, int tid) {
#pragma unroll
    for (int i = 0; i < 8; i++) {
        int q = tid + i * 256;
        int row = q >> 5, kq = q & 31;
        const float4* p = (const float4*)(src + (size_t)row * stride + k0 + kq * 4);
        r[i] = CG ? __ldcg(p) : __ldg(p);
    }
}
__device__ __forceinline__ void stsH(float2* hs, const float4 r[8], int tid) {
#pragma unroll
    for (int i = 0; i < 8; i++) {
        int q = tid + i * 256;
        int row = q >> 5, kq = q & 31;
        int sw = row ^ kq;
        hs[(2 * kq) * 64 + sw]     = make_float2(r[i].x, r[i].y);
        hs[(2 * kq + 1) * 64 + sw] = make_float2(r[i].z, r[i].w);
    }
}
template<int NI>
__device__ __forceinline__ void loadWf(float4 r[NI], const float* W, int K, int cBase, int k0, int tid) {
#pragma unroll
    for (int i = 0; i < NI; i++) {
        int q = tid + i * 256;
        int e = q >> 5, kq = q & 31;
        r[i] = __ldg((const float4*)(W + (size_t)(cBase + e) * K + k0 + kq * 4));
    }
}
template<int NI>
__device__ __forceinline__ void stsW(float* wc, const float4 r[NI], int tid) {
#pragma unroll
    for (int i = 0; i < NI; i++) {
        int q = tid + i * 256;
        int e = q >> 5, kq = q & 31;
        *(float4*)&wc[e * 128 + kq * 4] = r[i];
    }
}
template<int NO>
__device__ __forceinline__ void fcAcc(const float2* hs, const float* wc, int row, int cg, ull* acc) {
#pragma unroll 8
    for (int i = 0; i < 32; i++) {
        int sw = row ^ i;
        ull h0 = *(const ull*)&hs[(2 * i) * 64 + sw];
        ull h1 = *(const ull*)&hs[(2 * i + 1) * 64 + sw];
#pragma unroll
        for (int j = 0; j < NO; j++) {
            ulonglong2 wv = *(const ulonglong2*)&wc[(cg * NO + j) * 128 + i * 4];
            fma2(acc[j], h0, wv.x);
            fma2(acc[j], h1, wv.y);
        }
    }
}

// ================= decoder GRU phase: tf32 MMA ==============================
// block = 8 h-cols (24 gate rows). 8 warps = 4 M-tiles x 2 K-halves.
// Weights pre-converted tf32 (global); activations cvt'd during staging.
#define ALD 68
__device__ __forceinline__ void phase_gru_mma(
    const float* x, int Kx, const float* WihT,
    const float* hin, float* hout, const float* WhhT,
    const float* bih, const float* bhh,
    float* sm, int tid)
{
    float* wc0 = sm;                  // 24*68
    float* wc1 = sm + 1632;
    float* ac0 = sm + 3264;           // 64*68
    float* ac1 = ac0 + 4352;
    int lane = tid & 31, warp = tid >> 5;
    int g = lane >> 2, t4 = lane & 3;
    int mi = warp & 3, kh = warp >> 2;
    int cBase = blockIdx.x * 8;
    int xc = Kx / 64;
    int NC = xc + 16;

    float accI[3][4], accH[3][4];
#pragma unroll
    for (int n = 0; n < 3; n++)
#pragma unroll
        for (int i = 0; i < 4; i++) { accI[n][i] = 0.f; accH[n][i] = 0.f; }

    // stage chunk 0
#pragma unroll
    for (int i = 0; i < 4; i++) {
        int q = tid + i * 256, row = q >> 4, kq = q & 15;
        float4 v = __ldcg((const float4*)(x + (size_t)row * Kx + kq * 4));
        uint4 u = {cvtTF(v.x), cvtTF(v.y), cvtTF(v.z), cvtTF(v.w)};
        *(uint4*)&ac0[row * ALD + kq * 4] = u;
    }
#pragma unroll
    for (int i = 0; i < 2; i++) {
        int q = tid + i * 256;
        if (q < 384) {
            int row = q >> 4, kq = q & 15;
            int gRow = (row >> 3) * MM + cBase + (row & 7);
            float4 v = __ldg((const float4*)(WihT + (size_t)gRow * Kx + kq * 4));
            *(float4*)&wc0[row * ALD + kq * 4] = v;
        }
    }
    __syncthreads();

#pragma unroll 1
    for (int ch = 0; ch < NC; ch++) {
        float* ac  = (ch & 1) ? ac1 : ac0;
        float* wc  = (ch & 1) ? wc1 : wc0;
        float* acn = (ch & 1) ? ac0 : ac1;
        float* wcn = (ch & 1) ? wc0 : wc1;
        float4 pa[4]; float4 pw[2];
        if (ch + 1 < NC) {
            int nc = ch + 1;
            const float* asrc; const float* wsrc; int K2, off;
            if (nc < xc) { asrc = x;   wsrc = WihT; K2 = Kx; off = nc * 64; }
            else         { asrc = hin; wsrc = WhhT; K2 = MM; off = (nc - xc) * 64; }
#pragma unroll
            for (int i = 0; i < 4; i++) {
                int q = tid + i * 256, row = q >> 4, kq = q & 15;
                pa[i] = __ldcg((const float4*)(asrc + (size_t)row * K2 + off + kq * 4));
            }
#pragma unroll
            for (int i = 0; i < 2; i++) {
                int q = tid + i * 256;
                if (q < 384) {
                    int row = q >> 4, kq = q & 15;
                    int gRow = (row >> 3) * MM + cBase + (row & 7);
                    pw[i] = __ldg((const float4*)(wsrc + (size_t)gRow * K2 + off + kq * 4));
                }
            }
        }
        const unsigned* au = (const unsigned*)ac;
        const unsigned* wu = (const unsigned*)wc;
        int arow0 = (16 * mi + g) * ALD;
        int arow1 = arow0 + 8 * ALD;
        float (*acc)[4] = (ch < xc) ? accI : accH;
#pragma unroll
        for (int j = 0; j < 4; j++) {
            int k0 = (2 * j + kh) * 8;
            unsigned a0 = au[arow0 + k0 + t4];
            unsigned a1 = au[arow1 + k0 + t4];
            unsigned a2 = au[arow0 + k0 + t4 + 4];
            unsigned a3 = au[arow1 + k0 + t4 + 4];
#pragma unroll
            for (int nt = 0; nt < 3; nt++) {
                unsigned b0 = wu[(nt * 8 + g) * ALD + k0 + t4];
                unsigned b1 = wu[(nt * 8 + g) * ALD + k0 + t4 + 4];
                mma8(acc[nt], a0, a1, a2, a3, b0, b1);
            }
        }
        if (ch + 1 < NC) {
#pragma unroll
            for (int i = 0; i < 4; i++) {
                int q = tid + i * 256, row = q >> 4, kq = q & 15;
                uint4 u = {cvtTF(pa[i].x), cvtTF(pa[i].y), cvtTF(pa[i].z), cvtTF(pa[i].w)};
                *(uint4*)&acn[row * ALD + kq * 4] = u;
            }
#pragma unroll
            for (int i = 0; i < 2; i++) {
                int q = tid + i * 256;
                if (q < 384) {
                    int row = q >> 4, kq = q & 15;
                    *(float4*)&wcn[row * ALD + kq * 4] = pw[i];
                }
            }
        }
        __syncthreads();
    }

    // reduce K-halves (ac0 free: last chunk used ac1 since NC even)
    float* red = ac0;
    if (kh == 1) {
#pragma unroll
        for (int n = 0; n < 3; n++)
#pragma unroll
            for (int i = 0; i < 4; i++) {
                red[(mi * 32 + lane) * 24 + n * 4 + i]      = accI[n][i];
                red[(mi * 32 + lane) * 24 + 12 + n * 4 + i] = accH[n][i];
            }
    }
    __syncthreads();
    if (kh == 0) {
#pragma unroll
        for (int n = 0; n < 3; n++)
#pragma unroll
            for (int i = 0; i < 4; i++) {
                accI[n][i] += red[(mi * 32 + lane) * 24 + n * 4 + i];
                accH[n][i] += red[(mi * 32 + lane) * 24 + 12 + n * 4 + i];
            }
        int c0 = cBase + 2 * t4;
        float2 bri = *(const float2*)(bih + c0);
        float2 bzi = *(const float2*)(bih + MM + c0);
        float2 bni = *(const float2*)(bih + 2 * MM + c0);
        float2 brh = *(const float2*)(bhh + c0);
        float2 bzh = *(const float2*)(bhh + MM + c0);
        float2 bnh = *(const float2*)(bhh + 2 * MM + c0);
#pragma unroll
        for (int half = 0; half < 2; half++) {
            int row = 16 * mi + g + half * 8;
            float2 hp = __ldcg((const float2*)(hin + (size_t)row * MM + c0));
            float R0 = sigf(accI[0][2*half]   + bri.x + accH[0][2*half]   + brh.x);
            float R1 = sigf(accI[0][2*half+1] + bri.y + accH[0][2*half+1] + brh.y);
            float Z0 = sigf(accI[1][2*half]   + bzi.x + accH[1][2*half]   + bzh.x);
            float Z1 = sigf(accI[1][2*half+1] + bzi.y + accH[1][2*half+1] + bzh.y);
            float N0 = tanhf(accI[2][2*half]   + bni.x + R0 * (accH[2][2*half]   + bnh.x));
            float N1 = tanhf(accI[2][2*half+1] + bni.y + R1 * (accH[2][2*half+1] + bnh.y));
            float2 ho = {(1.f - Z0) * N0 + Z0 * hp.x, (1.f - Z1) * N1 + Z1 * hp.y};
            *(float2*)(hout + (size_t)row * MM + c0) = ho;
        }
    }
}

// ---------------- fc1 / ln / fc2 / softmax (unchanged, passing) -------------
__device__ __forceinline__ void phase_fc1(
    const float* A, const float* W, const float* bias,
    float* sm, int tid, int row, int cg)
{
    float* wcA = sm; float* wcB = sm + 2048;
    float2* hsA = (float2*)(sm + 4096); float2* hsB = hsA + 4096;
    int cBase = blockIdx.x * 16;
    ull acc[4] = {0ull, 0ull, 0ull, 0ull};

    float4 sh[8]; float4 swr[2];
    loadH<true>(sh, A, MM, 0, tid);
    loadWf<2>(swr, W, MM, cBase, 0, tid);
    stsH(hsA, sh, tid); stsW<2>(wcA, swr, tid);
    __syncthreads();
    float2* curH = hsA; float2* nxtH = hsB;
    float* curW = wcA; float* nxtW = wcB;
#pragma unroll 1
    for (int ch = 0; ch < 8; ch++) {
        if (ch < 7) {
            loadH<true>(sh, A, MM, (ch + 1) * 128, tid);
            loadWf<2>(swr, W, MM, cBase, (ch + 1) * 128, tid);
        }
        fcAcc<4>(curH, curW, row, cg, acc);
        if (ch < 7) { stsH(nxtH, sh, tid); stsW<2>(nxtW, swr, tid); }
        __syncthreads();
        float2* t1 = curH; curH = nxtH; nxtH = t1;
        float* t2 = curW; curW = nxtW; nxtW = t2;
    }
    int c = cBase + cg * 4;
    float4 bv = *(const float4*)(bias + c);
    float4 o = {rsum(acc[0]) + bv.x, rsum(acc[1]) + bv.y,
                rsum(acc[2]) + bv.z, rsum(acc[3]) + bv.w};
    *(float4*)(g_zpre + (size_t)row * LMM + c) = o;
}

__device__ __forceinline__ void phase_ln(const float* g, const float* bta, int tid)
{
    int b = blockIdx.x;
    float v[8];
    float s = 0.f, s2 = 0.f;
#pragma unroll
    for (int j = 0; j < 8; j++) {
        float t = __ldcg(&g_zpre[(size_t)b * LMM + tid + j * 256]);
        v[j] = t; s += t; s2 += t * t;
    }
    __shared__ float red[64];
#pragma unroll
    for (int o = 16; o; o >>= 1) {
        s += __shfl_down_sync(0xffffffffu, s, o);
        s2 += __shfl_down_sync(0xffffffffu, s2, o);
    }
    int w = tid >> 5, l = tid & 31;
    if (l == 0) { red[w] = s; red[32 + w] = s2; }
    __syncthreads();
    if (tid == 0) {
        float a = 0.f, a2 = 0.f;
        for (int i = 0; i < 8; i++) { a += red[i]; a2 += red[32 + i]; }
        red[0] = a; red[32] = a2;
    }
    __syncthreads();
    float mu = red[0] * (1.f / (float)LMM);
    float var = red[32] * (1.f / (float)LMM) - mu * mu;
    float rs = rsqrtf(var + 1e-5f);
#pragma unroll
    for (int j = 0; j < 8; j++) {
        int cc = tid + j * 256;
        float t = (v[j] - mu) * rs * g[cc] + bta[cc];
        g_z[(size_t)b * LMM + cc] = t * normcdff(t);
    }
}

__device__ __forceinline__ void phase_fc2(
    const float* W, const float* bias, float* out, int s,
    float* sm, int tid, int row, int cg)
{
    float* wcA = sm; float* wcB = sm + 1024;
    float2* hsA = (float2*)(sm + 2048); float2* hsB = hsA + 4096;
    int cBase = blockIdx.x * 8;
    ull acc[2] = {0ull, 0ull};

    float4 sh[8]; float4 swr[1];
    loadH<true>(sh, g_z, LMM, 0, tid);
    loadWf<1>(swr, W, LMM, cBase, 0, tid);
    stsH(hsA, sh, tid); stsW<1>(wcA, swr, tid);
    __syncthreads();
    float2* curH = hsA; float2* nxtH = hsB;
    float* curW = wcA; float* nxtW = wcB;
#pragma unroll 1
    for (int ch = 0; ch < 16; ch++) {
        if (ch < 15) {
            loadH<true>(sh, g_z, LMM, (ch + 1) * 128, tid);
            loadWf<1>(swr, W, LMM, cBase, (ch + 1) * 128, tid);
        }
        fcAcc<2>(curH, curW, row, cg, acc);
        if (ch < 15) { stsH(nxtH, sh, tid); stsW<1>(nxtW, swr, tid); }
        __syncthreads();
        float2* t1 = curH; curH = nxtH; nxtH = t1;
        float* t2 = curW; curW = nxtW; nxtW = t2;
    }
    int c = cBase + cg * 2;
    float2 bv = *(const float2*)(bias + c);
    float2 o = {rsum(acc[0]) + bv.x, rsum(acc[1]) + bv.y};
    *(float2*)(g_logits + (size_t)row * OO + c) = o;
    *(float2*)(out + ((size_t)row * TDEC + s) * OO + c) = o;
}

__device__ __forceinline__ void phase_softmax(float* yout, int tid)
{
    int b = blockIdx.x;
    float v0 = __ldcg(&g_logits[(size_t)b * OO + tid]);
    float v1 = __ldcg(&g_logits[(size_t)b * OO + 256 + tid]);
    __shared__ float sred[9];
    int w = tid >> 5, l = tid & 31;
    float m = fmaxf(v0, v1);
#pragma unroll
    for (int d = 16; d; d >>= 1) m = fmaxf(m, __shfl_down_sync(0xffffffffu, m, d));
    if (l == 0) sred[w] = m;
    __syncthreads();
    if (tid == 0) {
        float a = sred[0];
        for (int i = 1; i < 8; i++) a = fmaxf(a, sred[i]);
        sred[8] = a;
    }
    __syncthreads();
    float mx = sred[8];
    float e0 = expf(v0 - mx), e1 = expf(v1 - mx);
    float su = e0 + e1;
#pragma unroll
    for (int d = 16; d; d >>= 1) su += __shfl_down_sync(0xffffffffu, su, d);
    __syncthreads();
    if (l == 0) sred[w] = su;
    __syncthreads();
    if (tid == 0) {
        float a = 0.f;
        for (int i = 0; i < 8; i++) a += sred[i];
        sred[8] = a;
    }
    __syncthreads();
    float inv = 1.f / sred[8];
    yout[(size_t)b * OO + tid]       = e0 * inv;
    yout[(size_t)b * OO + 256 + tid] = e1 * inv;
}

__global__ void __launch_bounds__(256) dec_persist(
    float* __restrict__ out,
    float* yA, float* yB, float* h0A, float* h0B, float* h1A, float* h1B,
    const float* __restrict__ bih0, const float* __restrict__ bhh0,
    const float* __restrict__ bih1, const float* __restrict__ bhh1,
    const float* __restrict__ fc1w, const float* __restrict__ fc1b,
    const float* __restrict__ lng, const float* __restrict__ lnb,
    const float* __restrict__ fc2w, const float* __restrict__ fc2b)
{
    extern __shared__ float sm[];
    int tid = threadIdx.x, row = tid & 63, cg = tid >> 6;

    for (int s = 0; s < TDEC; s++) {
        const float* yin = (s & 1) ? yB : yA;
        float* yout      = (s & 1) ? yA : yB;
        const float* h0i = (s & 1) ? h0B : h0A;
        float* h0o       = (s & 1) ? h0A : h0B;
        const float* h1i = (s & 1) ? h1B : h1A;
        float* h1o       = (s & 1) ? h1A : h1B;

        phase_gru_mma(yin, OO, g_tWih0, h0i, h0o, g_tWhh0, bih0, bhh0, sm, tid);
        gbar();
        phase_gru_mma(h0o, MM, g_tWih1, h1i, h1o, g_tWhh1, bih1, bhh1, sm, tid);
        gbar();
        phase_fc1(h1o, fc1w, fc1b, sm, tid, row, cg);
        gbar();
        if (blockIdx.x < BB) phase_ln(lng, lnb, tid);
        gbar();
        if (blockIdx.x < BB) phase_fc2(fc2w, fc2b, out, s, sm, tid, row, cg);
        gbar();
        if (blockIdx.x < BB) phase_softmax(yout, tid);
        gbar();
    }
}

// ---------------- init / transpose / cvt / big GEMM ------------
__global__ void zero_init_kernel() {
    int i = blockIdx.x * blockDim.x + threadIdx.x;
    int stride = gridDim.x * blockDim.x;
    for (; i < BB * MM; i += stride) {
        g_e0A[i] = 0.f; g_e1A[i] = 0.f;
        g_hT0A[i] = 0.f; g_hT1A[i] = 0.f;
    }
}
__global__ void copy_y_kernel(const float* __restrict__ Y0) {
    int i = blockIdx.x * blockDim.x + threadIdx.x;
    if (i < BB * OO) g_yA[i] = Y0[i];
}
__global__ void transpose_x_kernel(const float* __restrict__ X) {
    int i = blockIdx.x * blockDim.x + threadIdx.x;
    int stride = gridDim.x * blockDim.x;
    const int total = TIN * BB * NIN;
    for (; i < total; i += stride) {
        int n = i % NIN;
        int r = i / NIN;
        int t = r / BB, b = r % BB;
        g_xt[i] = X[(b * TIN + t) * NIN + n];
    }
}
__global__ void cvt_w_kernel(const float* __restrict__ s, float* __restrict__ d, int n) {
    int i = blockIdx.x * blockDim.x + threadIdx.x;
    int st = gridDim.x * blockDim.x;
    for (; i < n; i += st) d[i] = __uint_as_float(cvtTF(s[i]));
}

__global__ void __launch_bounds__(256) gemm_big_kernel(
    const float* __restrict__ A, const float* __restrict__ W,
    const float* __restrict__ bias, float* __restrict__ C,
    int K, int Cn)
{
    __shared__ __align__(16) float As[16][132];
    __shared__ __align__(16) float Bs[16][132];
    int tid = threadIdx.x;
    int tx = tid & 15, ty = tid >> 4;
    int r0 = blockIdx.y * 128, c0 = blockIdx.x * 128;
    ull acc[8][4];
#pragma unroll
    for (int i = 0; i < 8; i++)
#pragma unroll
        for (int j = 0; j < 4; j++) acc[i][j] = 0ull;
    for (int k0 = 0; k0 < K; k0 += 16) {
#pragma unroll
        for (int i = 0; i < 2; i++) {
            int q = tid + i * 256;
            int rr = q >> 2, kq = q & 3;
            float4 v = *(const float4*)(A + (size_t)(r0 + rr) * K + k0 + kq * 4);
            As[kq * 4 + 0][rr] = v.x; As[kq * 4 + 1][rr] = v.y;
            As[kq * 4 + 2][rr] = v.z; As[kq * 4 + 3][rr] = v.w;
        }
#pragma unroll
        for (int i = 0; i < 2; i++) {
            int q = tid + i * 256;
            int wn = q >> 2, kq = q & 3;
            float4 v = *(const float4*)(W + (size_t)(c0 + wn) * K + k0 + kq * 4);
            Bs[kq * 4 + 0][wn] = v.x; Bs[kq * 4 + 1][wn] = v.y;
            Bs[kq * 4 + 2][wn] = v.z; Bs[kq * 4 + 3][wn] = v.w;
        }
        __syncthreads();
#pragma unroll
        for (int kk = 0; kk < 16; kk++) {
            ulonglong2 bq0 = *(ulonglong2*)&Bs[kk][tx * 8];
            ulonglong2 bq1 = *(ulonglong2*)&Bs[kk][tx * 8 + 4];
            ull bp[4] = {bq0.x, bq0.y, bq1.x, bq1.y};
            float4 a0 = *(float4*)&As[kk][ty * 8];
            float4 a1 = *(float4*)&As[kk][ty * 8 + 4];
            float av[8] = {a0.x, a0.y, a0.z, a0.w, a1.x, a1.y, a1.z, a1.w};
#pragma unroll
            for (int i = 0; i < 8; i++) {
                ull ap;
                asm("mov.b64 %0, {%1,%1};" : "=l"(ap) : "f"(av[i]));
#pragma unroll
                for (int j = 0; j < 4; j++) fma2(acc[i][j], ap, bp[j]);
            }
        }
        __syncthreads();
    }
    int c = c0 + tx * 8;
    float4 bv0 = *(const float4*)(bias + c);
    float4 bv1 = *(const float4*)(bias + c + 4);
#pragma unroll
    for (int i = 0; i < 8; i++) {
        int r = r0 + ty * 8 + i;
        float2 p0, p1, p2, p3;
        asm("mov.b64 {%0,%1}, %2;" : "=f"(p0.x), "=f"(p0.y) : "l"(acc[i][0]));
        asm("mov.b64 {%0,%1}, %2;" : "=f"(p1.x), "=f"(p1.y) : "l"(acc[i][1]));
        asm("mov.b64 {%0,%1}, %2;" : "=f"(p2.x), "=f"(p2.y) : "l"(acc[i][2]));
        asm("mov.b64 {%0,%1}, %2;" : "=f"(p3.x), "=f"(p3.y) : "l"(acc[i][3]));
        float4 o0 = {p0.x + bv0.x, p0.y + bv0.y, p1.x + bv0.z, p1.y + bv0.w};
        float4 o1 = {p2.x + bv1.x, p2.y + bv1.y, p3.x + bv1.z, p3.y + bv1.w};
        *(float4*)(C + (size_t)r * Cn + c) = o0;
        *(float4*)(C + (size_t)r * Cn + c + 4) = o1;
    }
}

// ---------------- host launch ----------------
#define DEC_SM ((2 * 3072 + 2 * 8192) * 4)      // 90112 B

extern "C" void kernel_launch(void* const* d_in, const int* in_sizes, int n_in,
                              void* d_out, int out_size)
{
    const float* X        = (const float*)d_in[0];
    const float* Y0       = (const float*)d_in[1];
    const float* enc_Wih0 = (const float*)d_in[2];
    const float* enc_Whh0 = (const float*)d_in[3];
    const float* enc_bih0 = (const float*)d_in[4];
    const float* enc_bhh0 = (const float*)d_in[5];
    const float* enc_Wih1 = (const float*)d_in[6];
    const float* enc_Whh1 = (const float*)d_in[7];
    const float* enc_bih1 = (const float*)d_in[8];
    const float* enc_bhh1 = (const float*)d_in[9];
    const float* dec_Wih0 = (const float*)d_in[10];
    const float* dec_Whh0 = (const float*)d_in[11];
    const float* dec_bih0 = (const float*)d_in[12];
    const float* dec_bhh0 = (const float*)d_in[13];
    const float* dec_Wih1 = (const float*)d_in[14];
    const float* dec_Whh1 = (const float*)d_in[15];
    const float* dec_bih1 = (const float*)d_in[16];
    const float* dec_bhh1 = (const float*)d_in[17];
    const float* fc1_w    = (const float*)d_in[18];
    const float* fc1_b    = (const float*)d_in[19];
    const float* ln_g     = (const float*)d_in[20];
    const float* ln_b     = (const float*)d_in[21];
    const float* fc2_w    = (const float*)d_in[22];
    const float* fc2_b    = (const float*)d_in[23];
    float* out = (float*)d_out;

    float *xt, *gi, *seq0, *e0A, *e0B, *e1A, *e1B, *yA, *yB;
    float *hT0A, *hT0B, *hT1A, *hT1B;
    float *tWih0, *tWhh0, *tWih1, *tWhh1;
    cudaGetSymbolAddress((void**)&xt,   g_xt);
    cudaGetSymbolAddress((void**)&gi,   g_gi);
    cudaGetSymbolAddress((void**)&seq0, g_seq0);
    cudaGetSymbolAddress((void**)&e0A,  g_e0A);
    cudaGetSymbolAddress((void**)&e0B,  g_e0B);
    cudaGetSymbolAddress((void**)&e1A,  g_e1A);
    cudaGetSymbolAddress((void**)&e1B,  g_e1B);
    cudaGetSymbolAddress((void**)&hT0A, g_hT0A);
    cudaGetSymbolAddress((void**)&hT0B, g_hT0B);
    cudaGetSymbolAddress((void**)&hT1A, g_hT1A);
    cudaGetSymbolAddress((void**)&hT1B, g_hT1B);
    cudaGetSymbolAddress((void**)&yA,   g_yA);
    cudaGetSymbolAddress((void**)&yB,   g_yB);
    cudaGetSymbolAddress((void**)&tWih0, g_tWih0);
    cudaGetSymbolAddress((void**)&tWhh0, g_tWhh0);
    cudaGetSymbolAddress((void**)&tWih1, g_tWih1);
    cudaGetSymbolAddress((void**)&tWhh1, g_tWhh1);

    cudaFuncSetAttribute(enc_mma,     cudaFuncAttributeMaxDynamicSharedMemorySize, ENC2_SM);
    cudaFuncSetAttribute(dec_persist, cudaFuncAttributeMaxDynamicSharedMemorySize, DEC_SM);

    zero_init_kernel<<<256, 256>>>();
    copy_y_kernel<<<(BB * OO + 255) / 256, 256>>>(Y0);
    transpose_x_kernel<<<2048, 256>>>(X);
    cvt_w_kernel<<<1024, 256>>>(dec_Wih0, tWih0, G3 * OO);
    cvt_w_kernel<<<1024, 256>>>(dec_Whh0, tWhh0, G3 * MM);
    cvt_w_kernel<<<1024, 256>>>(dec_Wih1, tWih1, G3 * MM);
    cvt_w_kernel<<<1024, 256>>>(dec_Whh1, tWhh1, G3 * MM);

    const int R = TIN * BB;

    // encoder layer 0
    gemm_big_kernel<<<dim3(G3 / 128, R / 128), 256>>>(xt, enc_Wih0, enc_bih0, gi, NIN, G3);
    {
        const float* w = enc_Whh0; const float* b = enc_bhh0; const float* gp = gi;
        float* hA = e0A; float* hB = e0B; float* hTA = hT0A; float* hTB = hT0B; float* sq = seq0;
        void* args[] = {&w, &b, &gp, &hA, &hB, &hTA, &hTB, &sq};
        cudaLaunchCooperativeKernel((void*)enc_mma, dim3(128), dim3(256), args, (size_t)ENC2_SM, (cudaStream_t)0);
    }

    // encoder layer 1
    gemm_big_kernel<<<dim3(G3 / 128, R / 128), 256>>>(seq0, enc_Wih1, enc_bih1, gi, MM, G3);
    {
        const float* w = enc_Whh1; const float* b = enc_bhh1; const float* gp = gi;
        float* hA = e1A; float* hB = e1B; float* hTA = hT1A; float* hTB = hT1B; float* sq = nullptr;
        void* args[] = {&w, &b, &gp, &hA, &hB, &hTA, &hTB, &sq};
        cudaLaunchCooperativeKernel((void*)enc_mma, dim3(128), dim3(256), args, (size_t)ENC2_SM, (cudaStream_t)0);
    }

    // decoder: one persistent kernel, all 64 steps
    {
        float* outp = out;
        void* args[] = {&outp, &yA, &yB, &e0A, &e0B, &e1A, &e1B,
                        (void*)&dec_bih0, (void*)&dec_bhh0,
                        (void*)&dec_bih1, (void*)&dec_bhh1,
                        (void*)&fc1_w, (void*)&fc1_b, (void*)&ln_g, (void*)&ln_b,
                        (void*)&fc2_w, (void*)&fc2_b};
        cudaLaunchCooperativeKernel((void*)dec_persist, dim3(128), dim3(256), args, (size_t)DEC_SM, (cudaStream_t)0);
    }
}

// round 15
// speedup vs baseline: 3.5052x; 1.1562x over previous
#include <cuda_runtime.h>
#include <math.h>

#define BB   64
#define TIN  128
#define NIN  256
#define MM   1024
#define OO   512
#define LMM  2048
#define TDEC 64
#define G3   3072
typedef unsigned long long ull;

// ---------------- scratch ----------------
__device__ float g_xt[TIN * BB * NIN];
__device__ float g_gi[TIN * BB * G3];
__device__ float g_seq0[TIN * BB * MM];
__device__ float g_e0A[BB * MM], g_e0B[BB * MM];
__device__ float g_e1A[BB * MM], g_e1B[BB * MM];
__device__ float g_hT0A[BB * MM], g_hT0B[BB * MM];
__device__ float g_hT1A[BB * MM], g_hT1B[BB * MM];
__device__ float g_yA[BB * OO], g_yB[BB * OO];
__device__ float g_zpre[BB * LMM];
__device__ float g_z[BB * LMM];
__device__ float g_l2p[2 * BB * OO];           // fc2 K-split partials
__device__ unsigned g_barc, g_barg;
// tf32 pre-converted weights
__device__ float g_tWih0[G3 * OO];
__device__ float g_tWhh0[G3 * MM];
__device__ float g_tWih1[G3 * MM];
__device__ float g_tWhh1[G3 * MM];
__device__ float g_tfc1[LMM * MM];
__device__ float g_tfc2[OO * LMM];

// ---------------- helpers ----------------
__device__ __forceinline__ float sigf(float x) { return 1.f / (1.f + expf(-x)); }
__device__ __forceinline__ unsigned cvtTF(float x) {
    unsigned u; asm("cvt.rna.tf32.f32 %0, %1;" : "=r"(u) : "f"(x)); return u;
}
__device__ __forceinline__ void mma8(float* c, unsigned a0, unsigned a1, unsigned a2, unsigned a3,
                                     unsigned b0, unsigned b1) {
    asm("mma.sync.aligned.m16n8k8.row.col.f32.tf32.tf32.f32 "
        "{%0,%1,%2,%3},{%4,%5,%6,%7},{%8,%9},{%0,%1,%2,%3};"
        : "+f"(c[0]), "+f"(c[1]), "+f"(c[2]), "+f"(c[3])
        : "r"(a0), "r"(a1), "r"(a2), "r"(a3), "r"(b0), "r"(b1));
}

__device__ __forceinline__ void gbar() {
    __syncthreads();
    __threadfence();
    if (threadIdx.x == 0) {
        unsigned gen = ((volatile unsigned*)&g_barg)[0];
        if (atomicAdd(&g_barc, 1u) == gridDim.x - 1) {
            g_barc = 0;
            __threadfence();
            atomicAdd(&g_barg, 1u);
        } else {
            while (((volatile unsigned*)&g_barg)[0] == gen) {}
        }
    }
    __syncthreads();
}

// ================= encoder: persistent tf32-MMA layer (passing) =============
#define WS_LD 1028
#define HT_LD 68
#define ENC2_SM ((24 * WS_LD + 2 * 64 * HT_LD) * 4)

__global__ void __launch_bounds__(256) enc_mma(
    const float* __restrict__ Whh, const float* __restrict__ bhh,
    const float* __restrict__ giB,
    float* hA, float* hB, float* hTA, float* hTB,
    float* seq)
{
    extern __shared__ float sm[];
    float* ws  = sm;
    float* ht0 = sm + 24 * WS_LD;
    float* ht1 = ht0 + 64 * HT_LD;
    int tid = threadIdx.x;
    int lane = tid & 31, warp = tid >> 5;
    int g = lane >> 2, t4 = lane & 3;
    int mi = warp & 3, kh = warp >> 2;
    int cBase = blockIdx.x * 8;

    for (int i = tid; i < 24 * 256; i += 256) {
        int r = i >> 8, kq = i & 255;
        int gRow = (r >> 3) * MM + cBase + (r & 7);
        float4 v = __ldg((const float4*)(Whh + (size_t)gRow * MM + kq * 4));
        uint4 u;
        u.x = cvtTF(v.x); u.y = cvtTF(v.y); u.z = cvtTF(v.z); u.w = cvtTF(v.w);
        *(uint4*)&ws[r * WS_LD + kq * 4] = u;
    }
    int c0 = cBase + 2 * t4;
    float br0 = bhh[c0],          br1 = bhh[c0 + 1];
    float bz0 = bhh[MM + c0],     bz1 = bhh[MM + c0 + 1];
    float bn0 = bhh[2 * MM + c0], bn1 = bhh[2 * MM + c0 + 1];
    __syncthreads();

    for (int t = 0; t < TIN; t++) {
        const float* hin  = (t & 1) ? hB : hA;
        float* hout       = (t & 1) ? hA : hB;
        const float* hinT = (t & 1) ? hTB : hTA;
        float* houtT      = (t & 1) ? hTA : hTB;

        float acc[3][4];
#pragma unroll
        for (int n = 0; n < 3; n++)
#pragma unroll
            for (int i = 0; i < 4; i++) acc[n][i] = 0.f;

#pragma unroll
        for (int i = 0; i < 4; i++) {
            int q = tid + i * 256;
            int row = q >> 4, kq = q & 15;
            float4 v = __ldcg((const float4*)(hinT + (size_t)row * MM + kq * 4));
            *(float4*)&ht0[row * HT_LD + kq * 4] = v;
        }
        __syncthreads();

#pragma unroll 1
        for (int ch = 0; ch < 16; ch++) {
            float* cur = (ch & 1) ? ht1 : ht0;
            float* nxt = (ch & 1) ? ht0 : ht1;
            float4 pf[4];
            if (ch < 15) {
#pragma unroll
                for (int i = 0; i < 4; i++) {
                    int q = tid + i * 256;
                    int row = q >> 4, kq = q & 15;
                    pf[i] = __ldcg((const float4*)(hinT + (size_t)row * MM + (ch + 1) * 64 + kq * 4));
                }
            }
            const unsigned* curu = (const unsigned*)cur;
            const unsigned* wsu  = (const unsigned*)ws;
            int arow0 = (16 * mi + g) * HT_LD;
            int arow1 = arow0 + 8 * HT_LD;
#pragma unroll
            for (int j = 0; j < 4; j++) {
                int k0 = (2 * j + kh) * 8;
                unsigned a0 = curu[arow0 + k0 + t4];
                unsigned a1 = curu[arow1 + k0 + t4];
                unsigned a2 = curu[arow0 + k0 + t4 + 4];
                unsigned a3 = curu[arow1 + k0 + t4 + 4];
                int kg = ch * 64 + k0 + t4;
#pragma unroll
                for (int nt = 0; nt < 3; nt++) {
                    unsigned b0 = wsu[(nt * 8 + g) * WS_LD + kg];
                    unsigned b1 = wsu[(nt * 8 + g) * WS_LD + kg + 4];
                    mma8(acc[nt], a0, a1, a2, a3, b0, b1);
                }
            }
            if (ch < 15) {
#pragma unroll
                for (int i = 0; i < 4; i++) {
                    int q = tid + i * 256;
                    int row = q >> 4, kq = q & 15;
                    *(float4*)&nxt[row * HT_LD + kq * 4] = pf[i];
                }
            }
            __syncthreads();
        }

        float* red = ht1;
        if (kh == 1) {
#pragma unroll
            for (int n = 0; n < 3; n++)
#pragma unroll
                for (int i = 0; i < 4; i++)
                    red[(mi * 32 + lane) * 12 + n * 4 + i] = acc[n][i];
        }
        __syncthreads();
        if (kh == 0) {
#pragma unroll
            for (int n = 0; n < 3; n++)
#pragma unroll
                for (int i = 0; i < 4; i++)
                    acc[n][i] += red[(mi * 32 + lane) * 12 + n * 4 + i];

            int rbase = 16 * mi + g;
#pragma unroll
            for (int half = 0; half < 2; half++) {
                int row = rbase + half * 8;
                float gr0 = acc[0][2 * half], gr1 = acc[0][2 * half + 1];
                float gz0 = acc[1][2 * half], gz1 = acc[1][2 * half + 1];
                float gn0 = acc[2][2 * half], gn1 = acc[2][2 * half + 1];
                const float* gi = giB + ((size_t)t * BB + row) * G3;
                float2 gir = *(const float2*)(gi + c0);
                float2 giz = *(const float2*)(gi + MM + c0);
                float2 gin = *(const float2*)(gi + 2 * MM + c0);
                float2 hp = __ldcg((const float2*)(hin + (size_t)row * MM + c0));
                float R0 = sigf(gir.x + gr0 + br0);
                float R1 = sigf(gir.y + gr1 + br1);
                float Z0 = sigf(giz.x + gz0 + bz0);
                float Z1 = sigf(giz.y + gz1 + bz1);
                float N0 = tanhf(gin.x + R0 * (gn0 + bn0));
                float N1 = tanhf(gin.y + R1 * (gn1 + bn1));
                float2 ho = {(1.f - Z0) * N0 + Z0 * hp.x, (1.f - Z1) * N1 + Z1 * hp.y};
                *(float2*)(hout + (size_t)row * MM + c0) = ho;
                float2 hoT = {__uint_as_float(cvtTF(ho.x)), __uint_as_float(cvtTF(ho.y))};
                *(float2*)(houtT + (size_t)row * MM + c0) = hoT;
                if (seq) *(float2*)(seq + ((size_t)t * BB + row) * MM + c0) = ho;
            }
        }
        gbar();
    }
}

// ================= decoder GRU phase: tf32 MMA (passing) ====================
#define ALD 68
__device__ __forceinline__ void phase_gru_mma(
    const float* x, int Kx, const float* WihT,
    const float* hin, float* hout, const float* WhhT,
    const float* bih, const float* bhh,
    float* sm, int tid)
{
    float* wc0 = sm;                  // 24*68
    float* wc1 = sm + 1632;
    float* ac0 = sm + 3264;           // 64*68
    float* ac1 = ac0 + 4352;
    int lane = tid & 31, warp = tid >> 5;
    int g = lane >> 2, t4 = lane & 3;
    int mi = warp & 3, kh = warp >> 2;
    int cBase = blockIdx.x * 8;
    int xc = Kx / 64;
    int NC = xc + 16;

    float accI[3][4], accH[3][4];
#pragma unroll
    for (int n = 0; n < 3; n++)
#pragma unroll
        for (int i = 0; i < 4; i++) { accI[n][i] = 0.f; accH[n][i] = 0.f; }

#pragma unroll
    for (int i = 0; i < 4; i++) {
        int q = tid + i * 256, row = q >> 4, kq = q & 15;
        float4 v = __ldcg((const float4*)(x + (size_t)row * Kx + kq * 4));
        uint4 u = {cvtTF(v.x), cvtTF(v.y), cvtTF(v.z), cvtTF(v.w)};
        *(uint4*)&ac0[row * ALD + kq * 4] = u;
    }
#pragma unroll
    for (int i = 0; i < 2; i++) {
        int q = tid + i * 256;
        if (q < 384) {
            int row = q >> 4, kq = q & 15;
            int gRow = (row >> 3) * MM + cBase + (row & 7);
            float4 v = __ldg((const float4*)(WihT + (size_t)gRow * Kx + kq * 4));
            *(float4*)&wc0[row * ALD + kq * 4] = v;
        }
    }
    __syncthreads();

#pragma unroll 1
    for (int ch = 0; ch < NC; ch++) {
        float* ac  = (ch & 1) ? ac1 : ac0;
        float* wc  = (ch & 1) ? wc1 : wc0;
        float* acn = (ch & 1) ? ac0 : ac1;
        float* wcn = (ch & 1) ? wc0 : wc1;
        float4 pa[4]; float4 pw[2];
        if (ch + 1 < NC) {
            int nc = ch + 1;
            const float* asrc; const float* wsrc; int K2, off;
            if (nc < xc) { asrc = x;   wsrc = WihT; K2 = Kx; off = nc * 64; }
            else         { asrc = hin; wsrc = WhhT; K2 = MM; off = (nc - xc) * 64; }
#pragma unroll
            for (int i = 0; i < 4; i++) {
                int q = tid + i * 256, row = q >> 4, kq = q & 15;
                pa[i] = __ldcg((const float4*)(asrc + (size_t)row * K2 + off + kq * 4));
            }
#pragma unroll
            for (int i = 0; i < 2; i++) {
                int q = tid + i * 256;
                if (q < 384) {
                    int row = q >> 4, kq = q & 15;
                    int gRow = (row >> 3) * MM + cBase + (row & 7);
                    pw[i] = __ldg((const float4*)(wsrc + (size_t)gRow * K2 + off + kq * 4));
                }
            }
        }
        const unsigned* au = (const unsigned*)ac;
        const unsigned* wu = (const unsigned*)wc;
        int arow0 = (16 * mi + g) * ALD;
        int arow1 = arow0 + 8 * ALD;
        float (*acc)[4] = (ch < xc) ? accI : accH;
#pragma unroll
        for (int j = 0; j < 4; j++) {
            int k0 = (2 * j + kh) * 8;
            unsigned a0 = au[arow0 + k0 + t4];
            unsigned a1 = au[arow1 + k0 + t4];
            unsigned a2 = au[arow0 + k0 + t4 + 4];
            unsigned a3 = au[arow1 + k0 + t4 + 4];
#pragma unroll
            for (int nt = 0; nt < 3; nt++) {
                unsigned b0 = wu[(nt * 8 + g) * ALD + k0 + t4];
                unsigned b1 = wu[(nt * 8 + g) * ALD + k0 + t4 + 4];
                mma8(acc[nt], a0, a1, a2, a3, b0, b1);
            }
        }
        if (ch + 1 < NC) {
#pragma unroll
            for (int i = 0; i < 4; i++) {
                int q = tid + i * 256, row = q >> 4, kq = q & 15;
                uint4 u = {cvtTF(pa[i].x), cvtTF(pa[i].y), cvtTF(pa[i].z), cvtTF(pa[i].w)};
                *(uint4*)&acn[row * ALD + kq * 4] = u;
            }
#pragma unroll
            for (int i = 0; i < 2; i++) {
                int q = tid + i * 256;
                if (q < 384) {
                    int row = q >> 4, kq = q & 15;
                    *(float4*)&wcn[row * ALD + kq * 4] = pw[i];
                }
            }
        }
        __syncthreads();
    }

    float* red = ac0;
    if (kh == 1) {
#pragma unroll
        for (int n = 0; n < 3; n++)
#pragma unroll
            for (int i = 0; i < 4; i++) {
                red[(mi * 32 + lane) * 24 + n * 4 + i]      = accI[n][i];
                red[(mi * 32 + lane) * 24 + 12 + n * 4 + i] = accH[n][i];
            }
    }
    __syncthreads();
    if (kh == 0) {
#pragma unroll
        for (int n = 0; n < 3; n++)
#pragma unroll
            for (int i = 0; i < 4; i++) {
                accI[n][i] += red[(mi * 32 + lane) * 24 + n * 4 + i];
                accH[n][i] += red[(mi * 32 + lane) * 24 + 12 + n * 4 + i];
            }
        int c0 = cBase + 2 * t4;
        float2 bri = *(const float2*)(bih + c0);
        float2 bzi = *(const float2*)(bih + MM + c0);
        float2 bni = *(const float2*)(bih + 2 * MM + c0);
        float2 brh = *(const float2*)(bhh + c0);
        float2 bzh = *(const float2*)(bhh + MM + c0);
        float2 bnh = *(const float2*)(bhh + 2 * MM + c0);
#pragma unroll
        for (int half = 0; half < 2; half++) {
            int row = 16 * mi + g + half * 8;
            float2 hp = __ldcg((const float2*)(hin + (size_t)row * MM + c0));
            float R0 = sigf(accI[0][2*half]   + bri.x + accH[0][2*half]   + brh.x);
            float R1 = sigf(accI[0][2*half+1] + bri.y + accH[0][2*half+1] + brh.y);
            float Z0 = sigf(accI[1][2*half]   + bzi.x + accH[1][2*half]   + bzh.x);
            float Z1 = sigf(accI[1][2*half+1] + bzi.y + accH[1][2*half+1] + bzh.y);
            float N0 = tanhf(accI[2][2*half]   + bni.x + R0 * (accH[2][2*half]   + bnh.x));
            float N1 = tanhf(accI[2][2*half+1] + bni.y + R1 * (accH[2][2*half+1] + bnh.y));
            float2 ho = {(1.f - Z0) * N0 + Z0 * hp.x, (1.f - Z1) * N1 + Z1 * hp.y};
            *(float2*)(hout + (size_t)row * MM + c0) = ho;
        }
    }
}

// ================= fc1: tf32 MMA (64x2048, K=1024) ==========================
// 128 blocks x 16 cols. 8 warps = 4 M-tiles x 2 K-halves; 2 N-tiles per warp.
__device__ __forceinline__ void phase_fc1_mma(
    const float* A, const float* WT, const float* bias, float* sm, int tid)
{
    float* wc0 = sm;                 // 16*68 = 1088
    float* wc1 = sm + 1088;
    float* ac0 = sm + 2176;          // 64*68 = 4352
    float* ac1 = ac0 + 4352;
    int lane = tid & 31, warp = tid >> 5;
    int g = lane >> 2, t4 = lane & 3;
    int mi = warp & 3, kh = warp >> 2;
    int cBase = blockIdx.x * 16;

    float acc[2][4];
#pragma unroll
    for (int n = 0; n < 2; n++)
#pragma unroll
        for (int i = 0; i < 4; i++) acc[n][i] = 0.f;

#pragma unroll
    for (int i = 0; i < 4; i++) {
        int q = tid + i * 256, row = q >> 4, kq = q & 15;
        float4 v = __ldcg((const float4*)(A + (size_t)row * MM + kq * 4));
        uint4 u = {cvtTF(v.x), cvtTF(v.y), cvtTF(v.z), cvtTF(v.w)};
        *(uint4*)&ac0[row * ALD + kq * 4] = u;
    }
    {
        int row = tid >> 4, kq = tid & 15;
        float4 v = __ldg((const float4*)(WT + (size_t)(cBase + row) * MM + kq * 4));
        *(float4*)&wc0[row * ALD + kq * 4] = v;
    }
    __syncthreads();

#pragma unroll 1
    for (int ch = 0; ch < 16; ch++) {
        float* ac  = (ch & 1) ? ac1 : ac0;
        float* wc  = (ch & 1) ? wc1 : wc0;
        float* acn = (ch & 1) ? ac0 : ac1;
        float* wcn = (ch & 1) ? wc0 : wc1;
        float4 pa[4]; float4 pw;
        if (ch < 15) {
            int off = (ch + 1) * 64;
#pragma unroll
            for (int i = 0; i < 4; i++) {
                int q = tid + i * 256, row = q >> 4, kq = q & 15;
                pa[i] = __ldcg((const float4*)(A + (size_t)row * MM + off + kq * 4));
            }
            {
                int row = tid >> 4, kq = tid & 15;
                pw = __ldg((const float4*)(WT + (size_t)(cBase + row) * MM + off + kq * 4));
            }
        }
        const unsigned* au = (const unsigned*)ac;
        const unsigned* wu = (const unsigned*)wc;
        int arow0 = (16 * mi + g) * ALD;
        int arow1 = arow0 + 8 * ALD;
#pragma unroll
        for (int j = 0; j < 4; j++) {
            int k0 = (2 * j + kh) * 8;
            unsigned a0 = au[arow0 + k0 + t4];
            unsigned a1 = au[arow1 + k0 + t4];
            unsigned a2 = au[arow0 + k0 + t4 + 4];
            unsigned a3 = au[arow1 + k0 + t4 + 4];
#pragma unroll
            for (int nt = 0; nt < 2; nt++) {
                unsigned b0 = wu[(nt * 8 + g) * ALD + k0 + t4];
                unsigned b1 = wu[(nt * 8 + g) * ALD + k0 + t4 + 4];
                mma8(acc[nt], a0, a1, a2, a3, b0, b1);
            }
        }
        if (ch < 15) {
#pragma unroll
            for (int i = 0; i < 4; i++) {
                int q = tid + i * 256, row = q >> 4, kq = q & 15;
                uint4 u = {cvtTF(pa[i].x), cvtTF(pa[i].y), cvtTF(pa[i].z), cvtTF(pa[i].w)};
                *(uint4*)&acn[row * ALD + kq * 4] = u;
            }
            {
                int row = tid >> 4, kq = tid & 15;
                *(float4*)&wcn[row * ALD + kq * 4] = pw;
            }
        }
        __syncthreads();
    }

    float* red = ac0;   // NC=16 even -> last chunk used ac1
    if (kh == 1) {
#pragma unroll
        for (int n = 0; n < 2; n++)
#pragma unroll
            for (int i = 0; i < 4; i++)
                red[(mi * 32 + lane) * 8 + n * 4 + i] = acc[n][i];
    }
    __syncthreads();
    if (kh == 0) {
#pragma unroll
        for (int n = 0; n < 2; n++)
#pragma unroll
            for (int i = 0; i < 4; i++)
                acc[n][i] += red[(mi * 32 + lane) * 8 + n * 4 + i];
#pragma unroll
        for (int half = 0; half < 2; half++) {
            int row = 16 * mi + g + half * 8;
#pragma unroll
            for (int nt = 0; nt < 2; nt++) {
                int c = cBase + nt * 8 + 2 * t4;
                float2 bv = *(const float2*)(bias + c);
                float2 o = {acc[nt][2 * half] + bv.x, acc[nt][2 * half + 1] + bv.y};
                *(float2*)(g_zpre + (size_t)row * LMM + c) = o;
            }
        }
    }
}

// ================= fc2: tf32 MMA, K-split + act hi/lo =======================
// 128 blocks = 64 col-groups (8 cols) x 2 K-splits (1024). Partials to g_l2p.
__device__ __forceinline__ void phase_fc2_mma(const float* WT, float* sm, int tid)
{
    float* wc0 = sm;                 // 8*68 = 544
    float* wc1 = sm + 544;
    float* hi0 = sm + 1088;          // 4352 each
    float* lo0 = hi0 + 4352;
    float* hi1 = lo0 + 4352;
    float* lo1 = hi1 + 4352;
    int lane = tid & 31, warp = tid >> 5;
    int g = lane >> 2, t4 = lane & 3;
    int mi = warp & 3, kh = warp >> 2;
    int cBase = (blockIdx.x >> 1) * 8;
    int ksp = blockIdx.x & 1;
    int kOff = ksp * 1024;

    float acc[4] = {0.f, 0.f, 0.f, 0.f};

#pragma unroll
    for (int i = 0; i < 4; i++) {
        int q = tid + i * 256, row = q >> 4, kq = q & 15;
        float4 v = __ldcg((const float4*)(g_z + (size_t)row * LMM + kOff + kq * 4));
        uint4 uh = {cvtTF(v.x), cvtTF(v.y), cvtTF(v.z), cvtTF(v.w)};
        uint4 ul = {cvtTF(v.x - __uint_as_float(uh.x)), cvtTF(v.y - __uint_as_float(uh.y)),
                    cvtTF(v.z - __uint_as_float(uh.z)), cvtTF(v.w - __uint_as_float(uh.w))};
        *(uint4*)&hi0[row * ALD + kq * 4] = uh;
        *(uint4*)&lo0[row * ALD + kq * 4] = ul;
    }
    if (tid < 128) {
        int row = tid >> 4, kq = tid & 15;
        float4 v = __ldg((const float4*)(WT + (size_t)(cBase + row) * LMM + kOff + kq * 4));
        *(float4*)&wc0[row * ALD + kq * 4] = v;
    }
    __syncthreads();

#pragma unroll 1
    for (int ch = 0; ch < 16; ch++) {
        float* hi  = (ch & 1) ? hi1 : hi0;
        float* lo  = (ch & 1) ? lo1 : lo0;
        float* wc  = (ch & 1) ? wc1 : wc0;
        float* hin_ = (ch & 1) ? hi0 : hi1;
        float* lon = (ch & 1) ? lo0 : lo1;
        float* wcn = (ch & 1) ? wc0 : wc1;
        float4 pa[4]; float4 pw;
        if (ch < 15) {
            int off = kOff + (ch + 1) * 64;
#pragma unroll
            for (int i = 0; i < 4; i++) {
                int q = tid + i * 256, row = q >> 4, kq = q & 15;
                pa[i] = __ldcg((const float4*)(g_z + (size_t)row * LMM + off + kq * 4));
            }
            if (tid < 128) {
                int row = tid >> 4, kq = tid & 15;
                pw = __ldg((const float4*)(WT + (size_t)(cBase + row) * LMM + off + kq * 4));
            }
        }
        const unsigned* hu = (const unsigned*)hi;
        const unsigned* lu = (const unsigned*)lo;
        const unsigned* wu = (const unsigned*)wc;
        int arow0 = (16 * mi + g) * ALD;
        int arow1 = arow0 + 8 * ALD;
#pragma unroll
        for (int j = 0; j < 4; j++) {
            int k0 = (2 * j + kh) * 8;
            unsigned b0 = wu[g * ALD + k0 + t4];
            unsigned b1 = wu[g * ALD + k0 + t4 + 4];
            mma8(acc, hu[arow0 + k0 + t4], hu[arow1 + k0 + t4],
                      hu[arow0 + k0 + t4 + 4], hu[arow1 + k0 + t4 + 4], b0, b1);
            mma8(acc, lu[arow0 + k0 + t4], lu[arow1 + k0 + t4],
                      lu[arow0 + k0 + t4 + 4], lu[arow1 + k0 + t4 + 4], b0, b1);
        }
        if (ch < 15) {
#pragma unroll
            for (int i = 0; i < 4; i++) {
                int q = tid + i * 256, row = q >> 4, kq = q & 15;
                uint4 uh = {cvtTF(pa[i].x), cvtTF(pa[i].y), cvtTF(pa[i].z), cvtTF(pa[i].w)};
                uint4 ul = {cvtTF(pa[i].x - __uint_as_float(uh.x)), cvtTF(pa[i].y - __uint_as_float(uh.y)),
                            cvtTF(pa[i].z - __uint_as_float(uh.z)), cvtTF(pa[i].w - __uint_as_float(uh.w))};
                *(uint4*)&hin_[row * ALD + kq * 4] = uh;
                *(uint4*)&lon[row * ALD + kq * 4] = ul;
            }
            if (tid < 128) {
                int row = tid >> 4, kq = tid & 15;
                *(float4*)&wcn[row * ALD + kq * 4] = pw;
            }
        }
        __syncthreads();
    }

    float* red = hi0;   // NC=16 even -> last chunk used hi1/lo1
    if (kh == 1) {
#pragma unroll
        for (int i = 0; i < 4; i++)
            red[(mi * 32 + lane) * 4 + i] = acc[i];
    }
    __syncthreads();
    if (kh == 0) {
#pragma unroll
        for (int i = 0; i < 4; i++) acc[i] += red[(mi * 32 + lane) * 4 + i];
        int c0 = cBase + 2 * t4;
#pragma unroll
        for (int half = 0; half < 2; half++) {
            int row = 16 * mi + g + half * 8;
            float2 o = {acc[2 * half], acc[2 * half + 1]};
            *(float2*)(g_l2p + (size_t)ksp * BB * OO + (size_t)row * OO + c0) = o;
        }
    }
}

// ---------------- ln / softmax ----------------
__device__ __forceinline__ void phase_ln(const float* g, const float* bta, int tid)
{
    int b = blockIdx.x;
    float v[8];
    float s = 0.f, s2 = 0.f;
#pragma unroll
    for (int j = 0; j < 8; j++) {
        float t = __ldcg(&g_zpre[(size_t)b * LMM + tid + j * 256]);
        v[j] = t; s += t; s2 += t * t;
    }
    __shared__ float red[64];
#pragma unroll
    for (int o = 16; o; o >>= 1) {
        s += __shfl_down_sync(0xffffffffu, s, o);
        s2 += __shfl_down_sync(0xffffffffu, s2, o);
    }
    int w = tid >> 5, l = tid & 31;
    if (l == 0) { red[w] = s; red[32 + w] = s2; }
    __syncthreads();
    if (tid == 0) {
        float a = 0.f, a2 = 0.f;
        for (int i = 0; i < 8; i++) { a += red[i]; a2 += red[32 + i]; }
        red[0] = a; red[32] = a2;
    }
    __syncthreads();
    float mu = red[0] * (1.f / (float)LMM);
    float var = red[32] * (1.f / (float)LMM) - mu * mu;
    float rs = rsqrtf(var + 1e-5f);
#pragma unroll
    for (int j = 0; j < 8; j++) {
        int cc = tid + j * 256;
        float t = (v[j] - mu) * rs * g[cc] + bta[cc];
        g_z[(size_t)b * LMM + cc] = t * normcdff(t);
    }
}

__device__ __forceinline__ void phase_softmax2(
    float* out, int s, float* yout, const float* fc2b, int tid)
{
    int b = blockIdx.x;
    float v0 = __ldcg(&g_l2p[(size_t)b * OO + tid])
             + __ldcg(&g_l2p[(size_t)BB * OO + b * OO + tid]) + fc2b[tid];
    float v1 = __ldcg(&g_l2p[(size_t)b * OO + 256 + tid])
             + __ldcg(&g_l2p[(size_t)BB * OO + b * OO + 256 + tid]) + fc2b[256 + tid];
    out[((size_t)b * TDEC + s) * OO + tid] = v0;
    out[((size_t)b * TDEC + s) * OO + 256 + tid] = v1;

    __shared__ float sred[9];
    int w = tid >> 5, l = tid & 31;
    float m = fmaxf(v0, v1);
#pragma unroll
    for (int d = 16; d; d >>= 1) m = fmaxf(m, __shfl_down_sync(0xffffffffu, m, d));
    if (l == 0) sred[w] = m;
    __syncthreads();
    if (tid == 0) {
        float a = sred[0];
        for (int i = 1; i < 8; i++) a = fmaxf(a, sred[i]);
        sred[8] = a;
    }
    __syncthreads();
    float mx = sred[8];
    float e0 = expf(v0 - mx), e1 = expf(v1 - mx);
    float su = e0 + e1;
#pragma unroll
    for (int d = 16; d; d >>= 1) su += __shfl_down_sync(0xffffffffu, su, d);
    __syncthreads();
    if (l == 0) sred[w] = su;
    __syncthreads();
    if (tid == 0) {
        float a = 0.f;
        for (int i = 0; i < 8; i++) a += sred[i];
        sred[8] = a;
    }
    __syncthreads();
    float inv = 1.f / sred[8];
    yout[(size_t)b * OO + tid]       = e0 * inv;
    yout[(size_t)b * OO + 256 + tid] = e1 * inv;
}

__global__ void __launch_bounds__(256) dec_persist(
    float* __restrict__ out,
    float* yA, float* yB, float* h0A, float* h0B, float* h1A, float* h1B,
    const float* __restrict__ bih0, const float* __restrict__ bhh0,
    const float* __restrict__ bih1, const float* __restrict__ bhh1,
    const float* __restrict__ fc1b,
    const float* __restrict__ lng, const float* __restrict__ lnb,
    const float* __restrict__ fc2b)
{
    extern __shared__ float sm[];
    int tid = threadIdx.x;

    for (int s = 0; s < TDEC; s++) {
        const float* yin = (s & 1) ? yB : yA;
        float* yout      = (s & 1) ? yA : yB;
        const float* h0i = (s & 1) ? h0B : h0A;
        float* h0o       = (s & 1) ? h0A : h0B;
        const float* h1i = (s & 1) ? h1B : h1A;
        float* h1o       = (s & 1) ? h1A : h1B;

        phase_gru_mma(yin, OO, g_tWih0, h0i, h0o, g_tWhh0, bih0, bhh0, sm, tid);
        gbar();
        phase_gru_mma(h0o, MM, g_tWih1, h1i, h1o, g_tWhh1, bih1, bhh1, sm, tid);
        gbar();
        phase_fc1_mma(h1o, g_tfc1, fc1b, sm, tid);
        gbar();
        if (blockIdx.x < BB) phase_ln(lng, lnb, tid);
        gbar();
        phase_fc2_mma(g_tfc2, sm, tid);
        gbar();
        if (blockIdx.x < BB) phase_softmax2(out, s, yout, fc2b, tid);
        gbar();
    }
}

// ---------------- init / transpose / cvt / big GEMM ------------
__global__ void zero_init_kernel() {
    int i = blockIdx.x * blockDim.x + threadIdx.x;
    int stride = gridDim.x * blockDim.x;
    for (; i < BB * MM; i += stride) {
        g_e0A[i] = 0.f; g_e1A[i] = 0.f;
        g_hT0A[i] = 0.f; g_hT1A[i] = 0.f;
    }
}
__global__ void copy_y_kernel(const float* __restrict__ Y0) {
    int i = blockIdx.x * blockDim.x + threadIdx.x;
    if (i < BB * OO) g_yA[i] = Y0[i];
}
__global__ void transpose_x_kernel(const float* __restrict__ X) {
    int i = blockIdx.x * blockDim.x + threadIdx.x;
    int stride = gridDim.x * blockDim.x;
    const int total = TIN * BB * NIN;
    for (; i < total; i += stride) {
        int n = i % NIN;
        int r = i / NIN;
        int t = r / BB, b = r % BB;
        g_xt[i] = X[(b * TIN + t) * NIN + n];
    }
}
__global__ void cvt_w_kernel(const float* __restrict__ s, float* __restrict__ d, int n) {
    int i = blockIdx.x * blockDim.x + threadIdx.x;
    int st = gridDim.x * blockDim.x;
    for (; i < n; i += st) d[i] = __uint_as_float(cvtTF(s[i]));
}

typedef unsigned long long ull2_t;
__device__ __forceinline__ void fma2(ull& d, ull a, ull b) {
    asm("fma.rn.f32x2 %0, %1, %2, %0;" : "+l"(d) : "l"(a), "l"(b));
}

__global__ void __launch_bounds__(256) gemm_big_kernel(
    const float* __restrict__ A, const float* __restrict__ W,
    const float* __restrict__ bias, float* __restrict__ C,
    int K, int Cn)
{
    __shared__ __align__(16) float As[16][132];
    __shared__ __align__(16) float Bs[16][132];
    int tid = threadIdx.x;
    int tx = tid & 15, ty = tid >> 4;
    int r0 = blockIdx.y * 128, c0 = blockIdx.x * 128;
    ull acc[8][4];
#pragma unroll
    for (int i = 0; i < 8; i++)
#pragma unroll
        for (int j = 0; j < 4; j++) acc[i][j] = 0ull;
    for (int k0 = 0; k0 < K; k0 += 16) {
#pragma unroll
        for (int i = 0; i < 2; i++) {
            int q = tid + i * 256;
            int rr = q >> 2, kq = q & 3;
            float4 v = *(const float4*)(A + (size_t)(r0 + rr) * K + k0 + kq * 4);
            As[kq * 4 + 0][rr] = v.x; As[kq * 4 + 1][rr] = v.y;
            As[kq * 4 + 2][rr] = v.z; As[kq * 4 + 3][rr] = v.w;
        }
#pragma unroll
        for (int i = 0; i < 2; i++) {
            int q = tid + i * 256;
            int wn = q >> 2, kq = q & 3;
            float4 v = *(const float4*)(W + (size_t)(c0 + wn) * K + k0 + kq * 4);
            Bs[kq * 4 + 0][wn] = v.x; Bs[kq * 4 + 1][wn] = v.y;
            Bs[kq * 4 + 2][wn] = v.z; Bs[kq * 4 + 3][wn] = v.w;
        }
        __syncthreads();
#pragma unroll
        for (int kk = 0; kk < 16; kk++) {
            ulonglong2 bq0 = *(ulonglong2*)&Bs[kk][tx * 8];
            ulonglong2 bq1 = *(ulonglong2*)&Bs[kk][tx * 8 + 4];
            ull bp[4] = {bq0.x, bq0.y, bq1.x, bq1.y};
            float4 a0 = *(float4*)&As[kk][ty * 8];
            float4 a1 = *(float4*)&As[kk][ty * 8 + 4];
            float av[8] = {a0.x, a0.y, a0.z, a0.w, a1.x, a1.y, a1.z, a1.w};
#pragma unroll
            for (int i = 0; i < 8; i++) {
                ull ap;
                asm("mov.b64 %0, {%1,%1};" : "=l"(ap) : "f"(av[i]));
#pragma unroll
                for (int j = 0; j < 4; j++) fma2(acc[i][j], ap, bp[j]);
            }
        }
        __syncthreads();
    }
    int c = c0 + tx * 8;
    float4 bv0 = *(const float4*)(bias + c);
    float4 bv1 = *(const float4*)(bias + c + 4);
#pragma unroll
    for (int i = 0; i < 8; i++) {
        int r = r0 + ty * 8 + i;
        float2 p0, p1, p2, p3;
        asm("mov.b64 {%0,%1}, %2;" : "=f"(p0.x), "=f"(p0.y) : "l"(acc[i][0]));
        asm("mov.b64 {%0,%1}, %2;" : "=f"(p1.x), "=f"(p1.y) : "l"(acc[i][1]));
        asm("mov.b64 {%0,%1}, %2;" : "=f"(p2.x), "=f"(p2.y) : "l"(acc[i][2]));
        asm("mov.b64 {%0,%1}, %2;" : "=f"(p3.x), "=f"(p3.y) : "l"(acc[i][3]));
        float4 o0 = {p0.x + bv0.x, p0.y + bv0.y, p1.x + bv0.z, p1.y + bv0.w};
        float4 o1 = {p2.x + bv1.x, p2.y + bv1.y, p3.x + bv1.z, p3.y + bv1.w};
        *(float4*)(C + (size_t)r * Cn + c) = o0;
        *(float4*)(C + (size_t)r * Cn + c + 4) = o1;
    }
}

// ---------------- host launch ----------------
#define DEC_SM ((2 * 3072 + 2 * 8192) * 4)      // 90112 B

extern "C" void kernel_launch(void* const* d_in, const int* in_sizes, int n_in,
                              void* d_out, int out_size)
{
    const float* X        = (const float*)d_in[0];
    const float* Y0       = (const float*)d_in[1];
    const float* enc_Wih0 = (const float*)d_in[2];
    const float* enc_Whh0 = (const float*)d_in[3];
    const float* enc_bih0 = (const float*)d_in[4];
    const float* enc_bhh0 = (const float*)d_in[5];
    const float* enc_Wih1 = (const float*)d_in[6];
    const float* enc_Whh1 = (const float*)d_in[7];
    const float* enc_bih1 = (const float*)d_in[8];
    const float* enc_bhh1 = (const float*)d_in[9];
    const float* dec_Wih0 = (const float*)d_in[10];
    const float* dec_Whh0 = (const float*)d_in[11];
    const float* dec_bih0 = (const float*)d_in[12];
    const float* dec_bhh0 = (const float*)d_in[13];
    const float* dec_Wih1 = (const float*)d_in[14];
    const float* dec_Whh1 = (const float*)d_in[15];
    const float* dec_bih1 = (const float*)d_in[16];
    const float* dec_bhh1 = (const float*)d_in[17];
    const float* fc1_w    = (const float*)d_in[18];
    const float* fc1_b    = (const float*)d_in[19];
    const float* ln_g     = (const float*)d_in[20];
    const float* ln_b     = (const float*)d_in[21];
    const float* fc2_w    = (const float*)d_in[22];
    const float* fc2_b    = (const float*)d_in[23];
    float* out = (float*)d_out;

    float *xt, *gi, *seq0, *e0A, *e0B, *e1A, *e1B, *yA, *yB;
    float *hT0A, *hT0B, *hT1A, *hT1B;
    float *tWih0, *tWhh0, *tWih1, *tWhh1, *tfc1, *tfc2;
    cudaGetSymbolAddress((void**)&xt,   g_xt);
    cudaGetSymbolAddress((void**)&gi,   g_gi);
    cudaGetSymbolAddress((void**)&seq0, g_seq0);
    cudaGetSymbolAddress((void**)&e0A,  g_e0A);
    cudaGetSymbolAddress((void**)&e0B,  g_e0B);
    cudaGetSymbolAddress((void**)&e1A,  g_e1A);
    cudaGetSymbolAddress((void**)&e1B,  g_e1B);
    cudaGetSymbolAddress((void**)&hT0A, g_hT0A);
    cudaGetSymbolAddress((void**)&hT0B, g_hT0B);
    cudaGetSymbolAddress((void**)&hT1A, g_hT1A);
    cudaGetSymbolAddress((void**)&hT1B, g_hT1B);
    cudaGetSymbolAddress((void**)&yA,   g_yA);
    cudaGetSymbolAddress((void**)&yB,   g_yB);
    cudaGetSymbolAddress((void**)&tWih0, g_tWih0);
    cudaGetSymbolAddress((void**)&tWhh0, g_tWhh0);
    cudaGetSymbolAddress((void**)&tWih1, g_tWih1);
    cudaGetSymbolAddress((void**)&tWhh1, g_tWhh1);
    cudaGetSymbolAddress((void**)&tfc1, g_tfc1);
    cudaGetSymbolAddress((void**)&tfc2, g_tfc2);

    cudaFuncSetAttribute(enc_mma,     cudaFuncAttributeMaxDynamicSharedMemorySize, ENC2_SM);
    cudaFuncSetAttribute(dec_persist, cudaFuncAttributeMaxDynamicSharedMemorySize, DEC_SM);

    zero_init_kernel<<<256, 256>>>();
    copy_y_kernel<<<(BB * OO + 255) / 256, 256>>>(Y0);
    transpose_x_kernel<<<2048, 256>>>(X);
    cvt_w_kernel<<<1024, 256>>>(dec_Wih0, tWih0, G3 * OO);
    cvt_w_kernel<<<1024, 256>>>(dec_Whh0, tWhh0, G3 * MM);
    cvt_w_kernel<<<1024, 256>>>(dec_Wih1, tWih1, G3 * MM);
    cvt_w_kernel<<<1024, 256>>>(dec_Whh1, tWhh1, G3 * MM);
    cvt_w_kernel<<<1024, 256>>>(fc1_w, tfc1, LMM * MM);
    cvt_w_kernel<<<1024, 256>>>(fc2_w, tfc2, OO * LMM);

    const int R = TIN * BB;

    // encoder layer 0
    gemm_big_kernel<<<dim3(G3 / 128, R / 128), 256>>>(xt, enc_Wih0, enc_bih0, gi, NIN, G3);
    {
        const float* w = enc_Whh0; const float* b = enc_bhh0; const float* gp = gi;
        float* hA = e0A; float* hB = e0B; float* hTA = hT0A; float* hTB = hT0B; float* sq = seq0;
        void* args[] = {&w, &b, &gp, &hA, &hB, &hTA, &hTB, &sq};
        cudaLaunchCooperativeKernel((void*)enc_mma, dim3(128), dim3(256), args, (size_t)ENC2_SM, (cudaStream_t)0);
    }

    // encoder layer 1
    gemm_big_kernel<<<dim3(G3 / 128, R / 128), 256>>>(seq0, enc_Wih1, enc_bih1, gi, MM, G3);
    {
        const float* w = enc_Whh1; const float* b = enc_bhh1; const float* gp = gi;
        float* hA = e1A; float* hB = e1B; float* hTA = hT1A; float* hTB = hT1B; float* sq = nullptr;
        void* args[] = {&w, &b, &gp, &hA, &hB, &hTA, &hTB, &sq};
        cudaLaunchCooperativeKernel((void*)enc_mma, dim3(128), dim3(256), args, (size_t)ENC2_SM, (cudaStream_t)0);
    }

    // decoder: one persistent kernel, all 64 steps
    {
        float* outp = out;
        void* args[] = {&outp, &yA, &yB, &e0A, &e0B, &e1A, &e1B,
                        (void*)&dec_bih0, (void*)&dec_bhh0,
                        (void*)&dec_bih1, (void*)&dec_bhh1,
                        (void*)&fc1_b, (void*)&ln_g, (void*)&ln_b, (void*)&fc2_b};
        cudaLaunchCooperativeKernel((void*)dec_persist, dim3(128), dim3(256), args, (size_t)DEC_SM, (cudaStream_t)0);
    }
}